// round 11
// baseline (speedup 1.0000x reference)
#include <cuda_runtime.h>

#define H 128
#define NMAX 50000
#define TEK 32          // edges per block (edge kernel)

// Scratch (no dynamic allocation allowed)
__device__ float g_agg[NMAX * H];
__device__ float g_dx[NMAX * 3];
__device__ float g_cnt[NMAX];
__device__ float g_P[NMAX * H];        // h @ We1[0:128]
__device__ float g_Q[NMAX * H];        // h @ We1[128:256]
__device__ float g_W2e[16 * 1024];     // We2 v4-swizzled tf32 (s-pairs packed)
__device__ float g_W2c[16 * 1024];     // Wc1 v4-swizzled
__device__ float g_W1p[16 * 1024];     // We1[0:128]   (v2 layout)
__device__ float g_W1q[16 * 1024];     // We1[128:256] (v2 layout)
__device__ float g_Wn2[16 * 1024];     // Wn2          (v2 layout)
__device__ float g_Wn1[32 * 1024];     // Wn1 (S=32, K=256, v2 layout)

__device__ __forceinline__ float silu(float v) {
    return v / (1.0f + __expf(-v));
}
__device__ __forceinline__ unsigned tf32u(float f) {
    unsigned r; asm("cvt.rna.tf32.f32 %0, %1;" : "=r"(r) : "f"(f));
    return r;
}
__device__ __forceinline__ float tf32f(float f) {
    return __uint_as_float(tf32u(f));
}
__device__ __forceinline__ void mma_tf32(float c[4],
    unsigned a0, unsigned a1, unsigned a2, unsigned a3,
    unsigned b0, unsigned b1)
{
    asm("mma.sync.aligned.m16n8k8.row.col.f32.tf32.tf32.f32 "
        "{%0,%1,%2,%3},{%4,%5,%6,%7},{%8,%9},{%0,%1,%2,%3};"
        : "+f"(c[0]), "+f"(c[1]), "+f"(c[2]), "+f"(c[3])
        : "r"(a0), "r"(a1), "r"(a2), "r"(a3), "r"(b0), "r"(b1));
}
__device__ __forceinline__ void ldsm4(unsigned &r0, unsigned &r1,
                                      unsigned &r2, unsigned &r3,
                                      unsigned addr)
{
    asm volatile("ldmatrix.sync.aligned.m8n8.x4.shared.b16 {%0,%1,%2,%3}, [%4];"
        : "=r"(r0), "=r"(r1), "=r"(r2), "=r"(r3) : "r"(addr));
}
__device__ __forceinline__ void redv4(float* p, float4 v) {
    asm volatile("red.global.add.v4.f32 [%0], {%1,%2,%3,%4};"
        :: "l"(p), "f"(v.x), "f"(v.y), "f"(v.z), "f"(v.w) : "memory");
}

__global__ void zero_kernel(int n) {
    int total = n * H + n * 3 + n;
    for (int i = blockIdx.x * blockDim.x + threadIdx.x; i < total;
         i += gridDim.x * blockDim.x) {
        if (i < n * H) g_agg[i] = 0.0f;
        else if (i < n * H + n * 3) g_dx[i - n * H] = 0.0f;
        else g_cnt[i - n * H - n * 3] = 0.0f;
    }
}

// v2 layout (pq/node kernels): dst[((tp*S+s)*32+lane)*2 + r]
__device__ __forceinline__ void swz_store(float* dst, const float* W,
                                          int S, int idx)
{
    int r = idx & 1;
    int lane = (idx >> 1) & 31;
    int sp = idx >> 6;             // tp*S + s
    int s = sp % S, tp = sp / S;
    int g = lane >> 2, tg = lane & 3;
    dst[idx] = tf32f(W[(8 * s + tg + 4 * r) * H + 8 * tp + g]);
}

// v4 layout (edge kernel): s-pairs packed for 128-bit loads.
// dst[((t*(S/2)+sp)*32+lane)*4 + q], q = 2*(s&1) + r, s = 2*sp + (q>>1)
__device__ __forceinline__ void swz_store4(float* dst, const float* W,
                                           int S, int idx)
{
    int q = idx & 3;
    int r = q & 1, so = q >> 1;
    int lane = (idx >> 2) & 31;
    int rest = idx >> 7;           // t*(S/2) + sp
    int S2 = S >> 1;
    int sp = rest % S2, t = rest / S2;
    int s = 2 * sp + so;
    int g = lane >> 2, tg = lane & 3;
    dst[idx] = tf32f(W[(8 * s + tg + 4 * r) * H + 8 * t + g]);
}

__global__ void prep_kernel(const float* __restrict__ We2,
                            const float* __restrict__ Wc1,
                            const float* __restrict__ Wn1,
                            const float* __restrict__ Wn2,
                            const float* __restrict__ We1)
{
    int i = blockIdx.x * blockDim.x + threadIdx.x;
    if (i < 16384)       swz_store4(g_W2e, We2, 16, i);
    else if (i < 32768)  swz_store4(g_W2c, Wc1, 16, i - 16384);
    else if (i < 49152)  swz_store(g_W1p, We1, 16, i - 32768);
    else if (i < 65536)  swz_store(g_W1q, We1 + 128 * H, 16, i - 49152);
    else if (i < 81920)  swz_store(g_Wn2, Wn2, 16, i - 65536);
    else if (i < 114688) swz_store(g_Wn1, Wn1, 32, i - 81920);
}

// ---------------------------------------------------------------------------
// PQ via tf32 MMA: 32 nodes/block, warps split N (32 cols each).
// ---------------------------------------------------------------------------
__global__ __launch_bounds__(128) void pq_kernel(
    const float* __restrict__ h, int n)
{
    __shared__ float s_tf[32][132];

    const int j = threadIdx.x;
    const int w = j >> 5, lane = j & 31;
    const int g = lane >> 2, tg = lane & 3;
    const int n0 = blockIdx.x * 32;

    const int rowA = lane & 15;
    const int colA = (lane & 16) ? 4 : 0;
    const unsigned baseA0 = (unsigned)__cvta_generic_to_shared(&s_tf[rowA][colA]);
    const unsigned baseA1 = (unsigned)__cvta_generic_to_shared(&s_tf[16 + rowA][colA]);

    #pragma unroll 4
    for (int e = 0; e < 32; e++) {
        int nd = n0 + e;
        s_tf[e][j] = (nd < n) ? tf32f(h[(long)nd * H + j]) : 0.f;
    }
    __syncthreads();

    float cc[4][2][4];

    // ---- P ----
    #pragma unroll
    for (int t = 0; t < 4; t++)
        #pragma unroll
        for (int mt = 0; mt < 2; mt++)
            #pragma unroll
            for (int q = 0; q < 4; q++) cc[t][mt][q] = 0.f;

    #pragma unroll 4
    for (int s = 0; s < 16; s++) {
        unsigned a00, a01, a02, a03, a10, a11, a12, a13;
        ldsm4(a00, a01, a02, a03, baseA0 + 32u * s);
        ldsm4(a10, a11, a12, a13, baseA1 + 32u * s);
        #pragma unroll
        for (int t = 0; t < 4; t++) {
            float2 bv = *(const float2*)&g_W1p[(((4 * w + t) * 16 + s) * 32 + lane) * 2];
            unsigned b0 = __float_as_uint(bv.x), b1 = __float_as_uint(bv.y);
            mma_tf32(cc[t][0], a00, a01, a02, a03, b0, b1);
            mma_tf32(cc[t][1], a10, a11, a12, a13, b0, b1);
        }
    }
    #pragma unroll
    for (int t = 0; t < 4; t++) {
        int col = 32 * w + 8 * t + 2 * tg;
        #pragma unroll
        for (int mt = 0; mt < 2; mt++) {
            int nd0 = n0 + g + 16 * mt, nd1 = nd0 + 8;
            if (nd0 < n) *(float2*)&g_P[(long)nd0 * H + col] =
                make_float2(cc[t][mt][0], cc[t][mt][1]);
            if (nd1 < n) *(float2*)&g_P[(long)nd1 * H + col] =
                make_float2(cc[t][mt][2], cc[t][mt][3]);
        }
    }

    // ---- Q ----
    #pragma unroll
    for (int t = 0; t < 4; t++)
        #pragma unroll
        for (int mt = 0; mt < 2; mt++)
            #pragma unroll
            for (int q = 0; q < 4; q++) cc[t][mt][q] = 0.f;

    #pragma unroll 4
    for (int s = 0; s < 16; s++) {
        unsigned a00, a01, a02, a03, a10, a11, a12, a13;
        ldsm4(a00, a01, a02, a03, baseA0 + 32u * s);
        ldsm4(a10, a11, a12, a13, baseA1 + 32u * s);
        #pragma unroll
        for (int t = 0; t < 4; t++) {
            float2 bv = *(const float2*)&g_W1q[(((4 * w + t) * 16 + s) * 32 + lane) * 2];
            unsigned b0 = __float_as_uint(bv.x), b1 = __float_as_uint(bv.y);
            mma_tf32(cc[t][0], a00, a01, a02, a03, b0, b1);
            mma_tf32(cc[t][1], a10, a11, a12, a13, b0, b1);
        }
    }
    #pragma unroll
    for (int t = 0; t < 4; t++) {
        int col = 32 * w + 8 * t + 2 * tg;
        #pragma unroll
        for (int mt = 0; mt < 2; mt++) {
            int nd0 = n0 + g + 16 * mt, nd1 = nd0 + 8;
            if (nd0 < n) *(float2*)&g_Q[(long)nd0 * H + col] =
                make_float2(cc[t][mt][0], cc[t][mt][1]);
            if (nd1 < n) *(float2*)&g_Q[(long)nd1 * H + col] =
                make_float2(cc[t][mt][2], cc[t][mt][3]);
        }
    }
}

// ---------------------------------------------------------------------------
// Edge kernel: TEK=32, warps split N; v4 B-loads (2 k8-steps per LDG.128);
// agg scatter via red.global.add.v4.f32.
// ---------------------------------------------------------------------------
__global__ __launch_bounds__(128, 8) void edge_kernel(
    const float* __restrict__ x, const int* __restrict__ ei, int E,
    const float* __restrict__ We1, const float* __restrict__ be1,
    const float* __restrict__ be2, const float* __restrict__ bc1,
    const float* __restrict__ Wc2, const float* __restrict__ bc2)
{
    __shared__ float s_tf[TEK][132];
    __shared__ float s_rel[TEK][3];
    __shared__ float s_d2[TEK];
    __shared__ int   s_row[TEK], s_col[TEK];
    __shared__ float s_gp[4][TEK];
    __shared__ float s_gate[TEK];

    const int j = threadIdx.x;
    const int w = j >> 5, lane = j & 31;
    const int g = lane >> 2, tg = lane & 3;
    const long e0 = (long)blockIdx.x * TEK;

    const int rowA = lane & 15;
    const int colA = (lane & 16) ? 4 : 0;
    const unsigned baseA0 =
        (unsigned)__cvta_generic_to_shared(&s_tf[rowA][colA]);
    const unsigned baseA1 =
        (unsigned)__cvta_generic_to_shared(&s_tf[16 + rowA][colA]);

    // Phase 0: per-edge scalars
    if (j < TEK) {
        long e = e0 + j;
        int r = -1, c = 0;
        float rx = 0.f, ry = 0.f, rz = 0.f, d2 = 0.f;
        if (e < E) {
            r = ei[e]; c = ei[E + e];
            rx = x[r * 3 + 0] - x[c * 3 + 0];
            ry = x[r * 3 + 1] - x[c * 3 + 1];
            rz = x[r * 3 + 2] - x[c * 3 + 2];
            d2 = rx * rx + ry * ry + rz * rz;
        }
        s_row[j] = r; s_col[j] = c; s_d2[j] = d2;
        s_rel[j][0] = rx; s_rel[j][1] = ry; s_rel[j][2] = rz;
    }
    __syncthreads();

    // Phase 1: layer-1 elementwise (thread j = column j), stored tf32
    {
        float wl = We1[256 * H + j];
        float b  = be1[j];
        #pragma unroll 4
        for (int e = 0; e < TEK; e++) {
            int r = s_row[e], c = s_col[e];
            float v = 0.f;
            if (r >= 0)
                v = silu(g_P[(long)r * H + j] + g_Q[(long)c * H + j]
                         + s_d2[e] * wl + b);
            s_tf[e][j] = tf32f(v);
        }
    }
    __syncthreads();

    float cc[4][2][4];

    // ---- GEMM1: f2 = silu(f1 @ We2 + be2) ----
    #pragma unroll
    for (int t = 0; t < 4; t++)
        #pragma unroll
        for (int mt = 0; mt < 2; mt++)
            #pragma unroll
            for (int q = 0; q < 4; q++) cc[t][mt][q] = 0.f;

    #pragma unroll 2
    for (int sp = 0; sp < 8; sp++) {
        unsigned e00, e01, e02, e03, e10, e11, e12, e13;
        unsigned o00, o01, o02, o03, o10, o11, o12, o13;
        ldsm4(e00, e01, e02, e03, baseA0 + 64u * sp);
        ldsm4(e10, e11, e12, e13, baseA1 + 64u * sp);
        ldsm4(o00, o01, o02, o03, baseA0 + 64u * sp + 32u);
        ldsm4(o10, o11, o12, o13, baseA1 + 64u * sp + 32u);
        #pragma unroll
        for (int t = 0; t < 4; t++) {
            float4 bv = *(const float4*)&g_W2e[(((4 * w + t) * 8 + sp) * 32 + lane) * 4];
            unsigned b0 = __float_as_uint(bv.x), b1 = __float_as_uint(bv.y);
            unsigned b2 = __float_as_uint(bv.z), b3 = __float_as_uint(bv.w);
            mma_tf32(cc[t][0], e00, e01, e02, e03, b0, b1);
            mma_tf32(cc[t][1], e10, e11, e12, e13, b0, b1);
            mma_tf32(cc[t][0], o00, o01, o02, o03, b2, b3);
            mma_tf32(cc[t][1], o10, o11, o12, o13, b2, b3);
        }
    }
    __syncthreads();   // all warps done reading s_tf (f1)

    // epilogue: silu + bias -> tf32 into s_tf
    #pragma unroll
    for (int t = 0; t < 4; t++) {
        int col = 32 * w + 8 * t + 2 * tg;
        float b0 = be2[col], b1 = be2[col + 1];
        #pragma unroll
        for (int mt = 0; mt < 2; mt++) {
            int r0 = g + 16 * mt, r1 = r0 + 8;
            s_tf[r0][col]     = tf32f(silu(cc[t][mt][0] + b0));
            s_tf[r0][col + 1] = tf32f(silu(cc[t][mt][1] + b1));
            s_tf[r1][col]     = tf32f(silu(cc[t][mt][2] + b0));
            s_tf[r1][col + 1] = tf32f(silu(cc[t][mt][3] + b1));
        }
    }
    __syncthreads();

    // agg scatter: vectorized red.v4; warp w covers edge 4*it+w, lane = 4 cols
    #pragma unroll
    for (int it = 0; it < 8; it++) {
        int e = 4 * it + w;
        int r = s_row[e];
        if (r >= 0) {
            float4 v = *(const float4*)&s_tf[e][lane * 4];
            redv4(&g_agg[(long)r * H + lane * 4], v);
        }
    }

    // ---- GEMM2: gate hidden = silu(f2 @ Wc1 + bc1), consumed in registers ----
    #pragma unroll
    for (int t = 0; t < 4; t++)
        #pragma unroll
        for (int mt = 0; mt < 2; mt++)
            #pragma unroll
            for (int q = 0; q < 4; q++) cc[t][mt][q] = 0.f;

    #pragma unroll 2
    for (int sp = 0; sp < 8; sp++) {
        unsigned e00, e01, e02, e03, e10, e11, e12, e13;
        unsigned o00, o01, o02, o03, o10, o11, o12, o13;
        ldsm4(e00, e01, e02, e03, baseA0 + 64u * sp);
        ldsm4(e10, e11, e12, e13, baseA1 + 64u * sp);
        ldsm4(o00, o01, o02, o03, baseA0 + 64u * sp + 32u);
        ldsm4(o10, o11, o12, o13, baseA1 + 64u * sp + 32u);
        #pragma unroll
        for (int t = 0; t < 4; t++) {
            float4 bv = *(const float4*)&g_W2c[(((4 * w + t) * 8 + sp) * 32 + lane) * 4];
            unsigned b0 = __float_as_uint(bv.x), b1 = __float_as_uint(bv.y);
            unsigned b2 = __float_as_uint(bv.z), b3 = __float_as_uint(bv.w);
            mma_tf32(cc[t][0], e00, e01, e02, e03, b0, b1);
            mma_tf32(cc[t][1], e10, e11, e12, e13, b0, b1);
            mma_tf32(cc[t][0], o00, o01, o02, o03, b2, b3);
            mma_tf32(cc[t][1], o10, o11, o12, o13, b2, b3);
        }
    }

    // gate partial dot with Wc2; thread covers edge rows g, g+8, g+16, g+24
    {
        float p0 = 0.f, p1 = 0.f, p2 = 0.f, p3 = 0.f;
        #pragma unroll
        for (int t = 0; t < 4; t++) {
            int col = 32 * w + 8 * t + 2 * tg;
            float w0 = Wc2[col], w1 = Wc2[col + 1];
            float b0 = bc1[col], b1 = bc1[col + 1];
            p0 += silu(cc[t][0][0] + b0) * w0 + silu(cc[t][0][1] + b1) * w1;
            p1 += silu(cc[t][0][2] + b0) * w0 + silu(cc[t][0][3] + b1) * w1;
            p2 += silu(cc[t][1][0] + b0) * w0 + silu(cc[t][1][1] + b1) * w1;
            p3 += silu(cc[t][1][2] + b0) * w0 + silu(cc[t][1][3] + b1) * w1;
        }
        p0 += __shfl_xor_sync(0xffffffffu, p0, 1);
        p0 += __shfl_xor_sync(0xffffffffu, p0, 2);
        p1 += __shfl_xor_sync(0xffffffffu, p1, 1);
        p1 += __shfl_xor_sync(0xffffffffu, p1, 2);
        p2 += __shfl_xor_sync(0xffffffffu, p2, 1);
        p2 += __shfl_xor_sync(0xffffffffu, p2, 2);
        p3 += __shfl_xor_sync(0xffffffffu, p3, 1);
        p3 += __shfl_xor_sync(0xffffffffu, p3, 2);
        if (tg == 0) {
            s_gp[w][g]      = p0;
            s_gp[w][g + 8]  = p1;
            s_gp[w][g + 16] = p2;
            s_gp[w][g + 24] = p3;
        }
    }
    __syncthreads();

    if (j < TEK)
        s_gate[j] = s_gp[0][j] + s_gp[1][j] + s_gp[2][j] + s_gp[3][j] + bc2[0];
    __syncthreads();

    {
        int e = j >> 2, c = j & 3;    // 128 threads = 32 edges x 4
        int r = s_row[e];
        if (r >= 0) {
            if (c < 3) atomicAdd(&g_dx[r * 3 + c], s_rel[e][c] * s_gate[e]);
            else       atomicAdd(&g_cnt[r], 1.0f);
        }
    }
}

// ---------------------------------------------------------------------------
// Node kernel via tf32 MMA (unchanged from R10)
// ---------------------------------------------------------------------------
__global__ __launch_bounds__(128) void node_kernel(
    const float* __restrict__ x, const float* __restrict__ h, int n,
    const float* __restrict__ bn1, const float* __restrict__ bn2,
    const float* __restrict__ gamma, const float* __restrict__ beta,
    float* __restrict__ xout, float* __restrict__ hout)
{
    __shared__ float s_tf[32][260];
    __shared__ float s_mu[32], s_rs[32];

    const int j = threadIdx.x;
    const int w = j >> 5, lane = j & 31;
    const int g = lane >> 2, tg = lane & 3;
    const int n0 = blockIdx.x * 32;

    const int rowA = lane & 15;
    const int colA = (lane & 16) ? 4 : 0;
    const unsigned baseA0 = (unsigned)__cvta_generic_to_shared(&s_tf[rowA][colA]);
    const unsigned baseA1 = (unsigned)__cvta_generic_to_shared(&s_tf[16 + rowA][colA]);

    #pragma unroll 4
    for (int e = 0; e < 32; e++) {
        int nd = n0 + e;
        float hv = 0.f, av = 0.f;
        if (nd < n) {
            float c = g_cnt[nd]; c = c < 1.0f ? 1.0f : c;
            hv = h[(long)nd * H + j];
            av = g_agg[(long)nd * H + j] / c;
        }
        s_tf[e][j]     = tf32f(hv);
        s_tf[e][H + j] = tf32f(av);
    }
    __syncthreads();

    float cc[4][2][4];

    // ---- GEMM1: n1 = silu(nin @ Wn1 + bn1), K=256 ----
    #pragma unroll
    for (int t = 0; t < 4; t++)
        #pragma unroll
        for (int mt = 0; mt < 2; mt++)
            #pragma unroll
            for (int q = 0; q < 4; q++) cc[t][mt][q] = 0.f;

    #pragma unroll 4
    for (int s = 0; s < 32; s++) {
        unsigned a00, a01, a02, a03, a10, a11, a12, a13;
        ldsm4(a00, a01, a02, a03, baseA0 + 32u * s);
        ldsm4(a10, a11, a12, a13, baseA1 + 32u * s);
        #pragma unroll
        for (int t = 0; t < 4; t++) {
            float2 bv = *(const float2*)&g_Wn1[(((4 * w + t) * 32 + s) * 32 + lane) * 2];
            unsigned b0 = __float_as_uint(bv.x), b1 = __float_as_uint(bv.y);
            mma_tf32(cc[t][0], a00, a01, a02, a03, b0, b1);
            mma_tf32(cc[t][1], a10, a11, a12, a13, b0, b1);
        }
    }
    __syncthreads();

    #pragma unroll
    for (int t = 0; t < 4; t++) {
        int col = 32 * w + 8 * t + 2 * tg;
        float b0 = bn1[col], b1 = bn1[col + 1];
        #pragma unroll
        for (int mt = 0; mt < 2; mt++) {
            int r0 = g + 16 * mt, r1 = r0 + 8;
            s_tf[r0][col]     = tf32f(silu(cc[t][mt][0] + b0));
            s_tf[r0][col + 1] = tf32f(silu(cc[t][mt][1] + b1));
            s_tf[r1][col]     = tf32f(silu(cc[t][mt][2] + b0));
            s_tf[r1][col + 1] = tf32f(silu(cc[t][mt][3] + b1));
        }
    }
    __syncthreads();

    // ---- GEMM2: dh = n1 @ Wn2 + bn2, K=128 ----
    #pragma unroll
    for (int t = 0; t < 4; t++)
        #pragma unroll
        for (int mt = 0; mt < 2; mt++)
            #pragma unroll
            for (int q = 0; q < 4; q++) cc[t][mt][q] = 0.f;

    #pragma unroll 4
    for (int s = 0; s < 16; s++) {
        unsigned a00, a01, a02, a03, a10, a11, a12, a13;
        ldsm4(a00, a01, a02, a03, baseA0 + 32u * s);
        ldsm4(a10, a11, a12, a13, baseA1 + 32u * s);
        #pragma unroll
        for (int t = 0; t < 4; t++) {
            float2 bv = *(const float2*)&g_Wn2[(((4 * w + t) * 16 + s) * 32 + lane) * 2];
            unsigned b0 = __float_as_uint(bv.x), b1 = __float_as_uint(bv.y);
            mma_tf32(cc[t][0], a00, a01, a02, a03, b0, b1);
            mma_tf32(cc[t][1], a10, a11, a12, a13, b0, b1);
        }
    }

    #pragma unroll
    for (int t = 0; t < 4; t++) {
        int col = 32 * w + 8 * t + 2 * tg;
        float b0 = bn2[col], b1 = bn2[col + 1];
        #pragma unroll
        for (int mt = 0; mt < 2; mt++) {
            int r0 = g + 16 * mt, r1 = r0 + 8;
            int nd0 = n0 + r0, nd1 = n0 + r1;
            float h00 = (nd0 < n) ? h[(long)nd0 * H + col]     : 0.f;
            float h01 = (nd0 < n) ? h[(long)nd0 * H + col + 1] : 0.f;
            float h10 = (nd1 < n) ? h[(long)nd1 * H + col]     : 0.f;
            float h11 = (nd1 < n) ? h[(long)nd1 * H + col + 1] : 0.f;
            s_tf[r0][H + col]     = h00 + cc[t][mt][0] + b0;
            s_tf[r0][H + col + 1] = h01 + cc[t][mt][1] + b1;
            s_tf[r1][H + col]     = h10 + cc[t][mt][2] + b0;
            s_tf[r1][H + col + 1] = h11 + cc[t][mt][3] + b1;
        }
    }
    __syncthreads();

    #pragma unroll
    for (int q = 0; q < 8; q++) {
        int e = w * 8 + q;
        float v0 = s_tf[e][H + lane];
        float v1 = s_tf[e][H + lane + 32];
        float v2 = s_tf[e][H + lane + 64];
        float v3 = s_tf[e][H + lane + 96];
        float s  = v0 + v1 + v2 + v3;
        float ss = v0 * v0 + v1 * v1 + v2 * v2 + v3 * v3;
        #pragma unroll
        for (int off = 16; off > 0; off >>= 1) {
            s  += __shfl_down_sync(0xffffffffu, s, off);
            ss += __shfl_down_sync(0xffffffffu, ss, off);
        }
        if (lane == 0) {
            float mu = s * (1.0f / H);
            float var = ss * (1.0f / H) - mu * mu;
            s_mu[e] = mu;
            s_rs[e] = rsqrtf(var + 1e-5f);
        }
    }
    __syncthreads();

    float gj = gamma[j], bj = beta[j];
    #pragma unroll 4
    for (int e = 0; e < 32; e++) {
        int nd = n0 + e;
        if (nd < n) {
            float v = (s_tf[e][H + j] - s_mu[e]) * s_rs[e] * gj + bj;
            hout[(long)nd * H + j] = silu(v);
            if (j < 3) {
                float c = g_cnt[nd]; c = c < 1.0f ? 1.0f : c;
                xout[nd * 3 + j] = x[nd * 3 + j] + g_dx[nd * 3 + j] / c;
            }
        }
    }
}

extern "C" void kernel_launch(void* const* d_in, const int* in_sizes, int n_in,
                              void* d_out, int out_size)
{
    const float* x    = (const float*)d_in[0];
    const float* h    = (const float*)d_in[1];
    const int*   ei   = (const int*)d_in[2];
    const float* We1  = (const float*)d_in[3];
    const float* be1  = (const float*)d_in[4];
    const float* We2  = (const float*)d_in[5];
    const float* be2  = (const float*)d_in[6];
    const float* Wc1  = (const float*)d_in[7];
    const float* bc1  = (const float*)d_in[8];
    const float* Wc2  = (const float*)d_in[9];
    const float* bc2  = (const float*)d_in[10];
    const float* Wn1  = (const float*)d_in[11];
    const float* bn1  = (const float*)d_in[12];
    const float* Wn2  = (const float*)d_in[13];
    const float* bn2  = (const float*)d_in[14];
    const float* gamma = (const float*)d_in[15];
    const float* beta  = (const float*)d_in[16];

    int n = in_sizes[0] / 3;       // 50000
    int E = in_sizes[2] / 2;       // 800000

    float* xout = (float*)d_out;              // [n,3]
    float* hout = xout + (size_t)n * 3;       // [n,128]

    zero_kernel<<<256, 256>>>(n);
    prep_kernel<<<448, 256>>>(We2, Wc1, Wn1, Wn2, We1);
    pq_kernel<<<(n + 31) / 32, 128>>>(h, n);
    edge_kernel<<<(E + TEK - 1) / TEK, 128>>>(x, ei, E,
                                              We1, be1, be2, bc1, Wc2, bc2);
    node_kernel<<<(n + 31) / 32, 128>>>(x, h, n, bn1, bn2,
                                        gamma, beta, xout, hout);
}

// round 12
// speedup vs baseline: 1.1801x; 1.1801x over previous
#include <cuda_runtime.h>

#define H 128
#define NMAX 50000
#define TEK 32          // edges per block (edge kernel)

// Scratch (no dynamic allocation allowed)
__device__ float g_agg[NMAX * H];
__device__ float g_dx[NMAX * 3];
__device__ float g_cnt[NMAX];
__device__ float g_P[NMAX * H];        // h @ We1[0:128]
__device__ float g_Q[NMAX * H];        // h @ We1[128:256]
__device__ float g_W2e[16 * 1024];     // We2 v4-swizzled tf32 (s-pairs packed)
__device__ float g_W2c[16 * 1024];     // Wc1 v4-swizzled
__device__ float g_W1p[16 * 1024];     // We1[0:128]   (v2 layout)
__device__ float g_W1q[16 * 1024];     // We1[128:256] (v2 layout)
__device__ float g_Wn2[16 * 1024];     // Wn2          (v2 layout)
__device__ float g_Wn1[32 * 1024];     // Wn1 (S=32, K=256, v2 layout)

__device__ __forceinline__ float silu(float v) {
    return v / (1.0f + __expf(-v));
}
__device__ __forceinline__ unsigned tf32u(float f) {
    unsigned r; asm("cvt.rna.tf32.f32 %0, %1;" : "=r"(r) : "f"(f));
    return r;
}
__device__ __forceinline__ float tf32f(float f) {
    return __uint_as_float(tf32u(f));
}
__device__ __forceinline__ void mma_tf32(float c[4],
    unsigned a0, unsigned a1, unsigned a2, unsigned a3,
    unsigned b0, unsigned b1)
{
    asm("mma.sync.aligned.m16n8k8.row.col.f32.tf32.tf32.f32 "
        "{%0,%1,%2,%3},{%4,%5,%6,%7},{%8,%9},{%0,%1,%2,%3};"
        : "+f"(c[0]), "+f"(c[1]), "+f"(c[2]), "+f"(c[3])
        : "r"(a0), "r"(a1), "r"(a2), "r"(a3), "r"(b0), "r"(b1));
}
__device__ __forceinline__ void ldsm4(unsigned &r0, unsigned &r1,
                                      unsigned &r2, unsigned &r3,
                                      unsigned addr)
{
    asm volatile("ldmatrix.sync.aligned.m8n8.x4.shared.b16 {%0,%1,%2,%3}, [%4];"
        : "=r"(r0), "=r"(r1), "=r"(r2), "=r"(r3) : "r"(addr));
}

__global__ void zero_kernel(int n) {
    int total = n * H + n * 3 + n;
    for (int i = blockIdx.x * blockDim.x + threadIdx.x; i < total;
         i += gridDim.x * blockDim.x) {
        if (i < n * H) g_agg[i] = 0.0f;
        else if (i < n * H + n * 3) g_dx[i - n * H] = 0.0f;
        else g_cnt[i - n * H - n * 3] = 0.0f;
    }
}

// v2 layout (pq/node kernels): dst[((tp*S+s)*32+lane)*2 + r]
__device__ __forceinline__ void swz_store(float* dst, const float* W,
                                          int S, int idx)
{
    int r = idx & 1;
    int lane = (idx >> 1) & 31;
    int sp = idx >> 6;             // tp*S + s
    int s = sp % S, tp = sp / S;
    int g = lane >> 2, tg = lane & 3;
    dst[idx] = tf32f(W[(8 * s + tg + 4 * r) * H + 8 * tp + g]);
}

// v4 layout (edge kernel): s-pairs packed for 128-bit loads.
__device__ __forceinline__ void swz_store4(float* dst, const float* W,
                                           int S, int idx)
{
    int q = idx & 3;
    int r = q & 1, so = q >> 1;
    int lane = (idx >> 2) & 31;
    int rest = idx >> 7;           // t*(S/2) + sp
    int S2 = S >> 1;
    int sp = rest % S2, t = rest / S2;
    int s = 2 * sp + so;
    int g = lane >> 2, tg = lane & 3;
    dst[idx] = tf32f(W[(8 * s + tg + 4 * r) * H + 8 * t + g]);
}

__global__ void prep_kernel(const float* __restrict__ We2,
                            const float* __restrict__ Wc1,
                            const float* __restrict__ Wn1,
                            const float* __restrict__ Wn2,
                            const float* __restrict__ We1)
{
    int i = blockIdx.x * blockDim.x + threadIdx.x;
    if (i < 16384)       swz_store4(g_W2e, We2, 16, i);
    else if (i < 32768)  swz_store4(g_W2c, Wc1, 16, i - 16384);
    else if (i < 49152)  swz_store(g_W1p, We1, 16, i - 32768);
    else if (i < 65536)  swz_store(g_W1q, We1 + 128 * H, 16, i - 49152);
    else if (i < 81920)  swz_store(g_Wn2, Wn2, 16, i - 65536);
    else if (i < 114688) swz_store(g_Wn1, Wn1, 32, i - 81920);
}

// ---------------------------------------------------------------------------
// PQ via tf32 MMA: 32 nodes/block, warps split N (32 cols each).
// ---------------------------------------------------------------------------
__global__ __launch_bounds__(128) void pq_kernel(
    const float* __restrict__ h, int n)
{
    __shared__ float s_tf[32][132];

    const int j = threadIdx.x;
    const int w = j >> 5, lane = j & 31;
    const int g = lane >> 2, tg = lane & 3;
    const int n0 = blockIdx.x * 32;

    const int rowA = lane & 15;
    const int colA = (lane & 16) ? 4 : 0;
    const unsigned baseA0 = (unsigned)__cvta_generic_to_shared(&s_tf[rowA][colA]);
    const unsigned baseA1 = (unsigned)__cvta_generic_to_shared(&s_tf[16 + rowA][colA]);

    #pragma unroll 4
    for (int e = 0; e < 32; e++) {
        int nd = n0 + e;
        s_tf[e][j] = (nd < n) ? tf32f(h[(long)nd * H + j]) : 0.f;
    }
    __syncthreads();

    float cc[4][2][4];

    // ---- P ----
    #pragma unroll
    for (int t = 0; t < 4; t++)
        #pragma unroll
        for (int mt = 0; mt < 2; mt++)
            #pragma unroll
            for (int q = 0; q < 4; q++) cc[t][mt][q] = 0.f;

    #pragma unroll 4
    for (int s = 0; s < 16; s++) {
        unsigned a00, a01, a02, a03, a10, a11, a12, a13;
        ldsm4(a00, a01, a02, a03, baseA0 + 32u * s);
        ldsm4(a10, a11, a12, a13, baseA1 + 32u * s);
        #pragma unroll
        for (int t = 0; t < 4; t++) {
            float2 bv = *(const float2*)&g_W1p[(((4 * w + t) * 16 + s) * 32 + lane) * 2];
            unsigned b0 = __float_as_uint(bv.x), b1 = __float_as_uint(bv.y);
            mma_tf32(cc[t][0], a00, a01, a02, a03, b0, b1);
            mma_tf32(cc[t][1], a10, a11, a12, a13, b0, b1);
        }
    }
    #pragma unroll
    for (int t = 0; t < 4; t++) {
        int col = 32 * w + 8 * t + 2 * tg;
        #pragma unroll
        for (int mt = 0; mt < 2; mt++) {
            int nd0 = n0 + g + 16 * mt, nd1 = nd0 + 8;
            if (nd0 < n) *(float2*)&g_P[(long)nd0 * H + col] =
                make_float2(cc[t][mt][0], cc[t][mt][1]);
            if (nd1 < n) *(float2*)&g_P[(long)nd1 * H + col] =
                make_float2(cc[t][mt][2], cc[t][mt][3]);
        }
    }

    // ---- Q ----
    #pragma unroll
    for (int t = 0; t < 4; t++)
        #pragma unroll
        for (int mt = 0; mt < 2; mt++)
            #pragma unroll
            for (int q = 0; q < 4; q++) cc[t][mt][q] = 0.f;

    #pragma unroll 4
    for (int s = 0; s < 16; s++) {
        unsigned a00, a01, a02, a03, a10, a11, a12, a13;
        ldsm4(a00, a01, a02, a03, baseA0 + 32u * s);
        ldsm4(a10, a11, a12, a13, baseA1 + 32u * s);
        #pragma unroll
        for (int t = 0; t < 4; t++) {
            float2 bv = *(const float2*)&g_W1q[(((4 * w + t) * 16 + s) * 32 + lane) * 2];
            unsigned b0 = __float_as_uint(bv.x), b1 = __float_as_uint(bv.y);
            mma_tf32(cc[t][0], a00, a01, a02, a03, b0, b1);
            mma_tf32(cc[t][1], a10, a11, a12, a13, b0, b1);
        }
    }
    #pragma unroll
    for (int t = 0; t < 4; t++) {
        int col = 32 * w + 8 * t + 2 * tg;
        #pragma unroll
        for (int mt = 0; mt < 2; mt++) {
            int nd0 = n0 + g + 16 * mt, nd1 = nd0 + 8;
            if (nd0 < n) *(float2*)&g_Q[(long)nd0 * H + col] =
                make_float2(cc[t][mt][0], cc[t][mt][1]);
            if (nd1 < n) *(float2*)&g_Q[(long)nd1 * H + col] =
                make_float2(cc[t][mt][2], cc[t][mt][3]);
        }
    }
}

// ---------------------------------------------------------------------------
// Edge kernel: R10 structure + v4 B-loads ONLY (no launch cap, no redv4).
// ---------------------------------------------------------------------------
__global__ __launch_bounds__(128) void edge_kernel(
    const float* __restrict__ x, const int* __restrict__ ei, int E,
    const float* __restrict__ We1, const float* __restrict__ be1,
    const float* __restrict__ be2, const float* __restrict__ bc1,
    const float* __restrict__ Wc2, const float* __restrict__ bc2)
{
    __shared__ float s_tf[TEK][132];
    __shared__ float s_rel[TEK][3];
    __shared__ float s_d2[TEK];
    __shared__ int   s_row[TEK], s_col[TEK];
    __shared__ float s_gp[4][TEK];
    __shared__ float s_gate[TEK];

    const int j = threadIdx.x;
    const int w = j >> 5, lane = j & 31;
    const int g = lane >> 2, tg = lane & 3;
    const long e0 = (long)blockIdx.x * TEK;

    const int rowA = lane & 15;
    const int colA = (lane & 16) ? 4 : 0;
    const unsigned baseA0 =
        (unsigned)__cvta_generic_to_shared(&s_tf[rowA][colA]);
    const unsigned baseA1 =
        (unsigned)__cvta_generic_to_shared(&s_tf[16 + rowA][colA]);

    // Phase 0: per-edge scalars
    if (j < TEK) {
        long e = e0 + j;
        int r = -1, c = 0;
        float rx = 0.f, ry = 0.f, rz = 0.f, d2 = 0.f;
        if (e < E) {
            r = ei[e]; c = ei[E + e];
            rx = x[r * 3 + 0] - x[c * 3 + 0];
            ry = x[r * 3 + 1] - x[c * 3 + 1];
            rz = x[r * 3 + 2] - x[c * 3 + 2];
            d2 = rx * rx + ry * ry + rz * rz;
        }
        s_row[j] = r; s_col[j] = c; s_d2[j] = d2;
        s_rel[j][0] = rx; s_rel[j][1] = ry; s_rel[j][2] = rz;
    }
    __syncthreads();

    // Phase 1: layer-1 elementwise (thread j = column j), stored tf32
    {
        float wl = We1[256 * H + j];
        float b  = be1[j];
        #pragma unroll 4
        for (int e = 0; e < TEK; e++) {
            int r = s_row[e], c = s_col[e];
            float v = 0.f;
            if (r >= 0)
                v = silu(g_P[(long)r * H + j] + g_Q[(long)c * H + j]
                         + s_d2[e] * wl + b);
            s_tf[e][j] = tf32f(v);
        }
    }
    __syncthreads();

    float cc[4][2][4];

    // ---- GEMM1: f2 = silu(f1 @ We2 + be2) ----
    #pragma unroll
    for (int t = 0; t < 4; t++)
        #pragma unroll
        for (int mt = 0; mt < 2; mt++)
            #pragma unroll
            for (int q = 0; q < 4; q++) cc[t][mt][q] = 0.f;

    #pragma unroll 2
    for (int sp = 0; sp < 8; sp++) {
        unsigned e00, e01, e02, e03, e10, e11, e12, e13;
        unsigned o00, o01, o02, o03, o10, o11, o12, o13;
        ldsm4(e00, e01, e02, e03, baseA0 + 64u * sp);
        ldsm4(e10, e11, e12, e13, baseA1 + 64u * sp);
        ldsm4(o00, o01, o02, o03, baseA0 + 64u * sp + 32u);
        ldsm4(o10, o11, o12, o13, baseA1 + 64u * sp + 32u);
        #pragma unroll
        for (int t = 0; t < 4; t++) {
            float4 bv = *(const float4*)&g_W2e[(((4 * w + t) * 8 + sp) * 32 + lane) * 4];
            unsigned b0 = __float_as_uint(bv.x), b1 = __float_as_uint(bv.y);
            unsigned b2 = __float_as_uint(bv.z), b3 = __float_as_uint(bv.w);
            mma_tf32(cc[t][0], e00, e01, e02, e03, b0, b1);
            mma_tf32(cc[t][1], e10, e11, e12, e13, b0, b1);
            mma_tf32(cc[t][0], o00, o01, o02, o03, b2, b3);
            mma_tf32(cc[t][1], o10, o11, o12, o13, b2, b3);
        }
    }
    __syncthreads();   // all warps done reading s_tf (f1)

    // epilogue: silu + bias -> tf32 into s_tf
    #pragma unroll
    for (int t = 0; t < 4; t++) {
        int col = 32 * w + 8 * t + 2 * tg;
        float b0 = be2[col], b1 = be2[col + 1];
        #pragma unroll
        for (int mt = 0; mt < 2; mt++) {
            int r0 = g + 16 * mt, r1 = r0 + 8;
            s_tf[r0][col]     = tf32f(silu(cc[t][mt][0] + b0));
            s_tf[r0][col + 1] = tf32f(silu(cc[t][mt][1] + b1));
            s_tf[r1][col]     = tf32f(silu(cc[t][mt][2] + b0));
            s_tf[r1][col + 1] = tf32f(silu(cc[t][mt][3] + b1));
        }
    }
    __syncthreads();

    // agg scatter (coalesced: thread j = column j), tf32-rounded f2
    #pragma unroll 4
    for (int e = 0; e < TEK; e++) {
        int r = s_row[e];
        if (r >= 0) atomicAdd(&g_agg[(long)r * H + j], s_tf[e][j]);
    }

    // ---- GEMM2: gate hidden = silu(f2 @ Wc1 + bc1), consumed in registers ----
    #pragma unroll
    for (int t = 0; t < 4; t++)
        #pragma unroll
        for (int mt = 0; mt < 2; mt++)
            #pragma unroll
            for (int q = 0; q < 4; q++) cc[t][mt][q] = 0.f;

    #pragma unroll 2
    for (int sp = 0; sp < 8; sp++) {
        unsigned e00, e01, e02, e03, e10, e11, e12, e13;
        unsigned o00, o01, o02, o03, o10, o11, o12, o13;
        ldsm4(e00, e01, e02, e03, baseA0 + 64u * sp);
        ldsm4(e10, e11, e12, e13, baseA1 + 64u * sp);
        ldsm4(o00, o01, o02, o03, baseA0 + 64u * sp + 32u);
        ldsm4(o10, o11, o12, o13, baseA1 + 64u * sp + 32u);
        #pragma unroll
        for (int t = 0; t < 4; t++) {
            float4 bv = *(const float4*)&g_W2c[(((4 * w + t) * 8 + sp) * 32 + lane) * 4];
            unsigned b0 = __float_as_uint(bv.x), b1 = __float_as_uint(bv.y);
            unsigned b2 = __float_as_uint(bv.z), b3 = __float_as_uint(bv.w);
            mma_tf32(cc[t][0], e00, e01, e02, e03, b0, b1);
            mma_tf32(cc[t][1], e10, e11, e12, e13, b0, b1);
            mma_tf32(cc[t][0], o00, o01, o02, o03, b2, b3);
            mma_tf32(cc[t][1], o10, o11, o12, o13, b2, b3);
        }
    }

    // gate partial dot with Wc2; thread covers edge rows g, g+8, g+16, g+24
    {
        float p0 = 0.f, p1 = 0.f, p2 = 0.f, p3 = 0.f;
        #pragma unroll
        for (int t = 0; t < 4; t++) {
            int col = 32 * w + 8 * t + 2 * tg;
            float w0 = Wc2[col], w1 = Wc2[col + 1];
            float b0 = bc1[col], b1 = bc1[col + 1];
            p0 += silu(cc[t][0][0] + b0) * w0 + silu(cc[t][0][1] + b1) * w1;
            p1 += silu(cc[t][0][2] + b0) * w0 + silu(cc[t][0][3] + b1) * w1;
            p2 += silu(cc[t][1][0] + b0) * w0 + silu(cc[t][1][1] + b1) * w1;
            p3 += silu(cc[t][1][2] + b0) * w0 + silu(cc[t][1][3] + b1) * w1;
        }
        p0 += __shfl_xor_sync(0xffffffffu, p0, 1);
        p0 += __shfl_xor_sync(0xffffffffu, p0, 2);
        p1 += __shfl_xor_sync(0xffffffffu, p1, 1);
        p1 += __shfl_xor_sync(0xffffffffu, p1, 2);
        p2 += __shfl_xor_sync(0xffffffffu, p2, 1);
        p2 += __shfl_xor_sync(0xffffffffu, p2, 2);
        p3 += __shfl_xor_sync(0xffffffffu, p3, 1);
        p3 += __shfl_xor_sync(0xffffffffu, p3, 2);
        if (tg == 0) {
            s_gp[w][g]      = p0;
            s_gp[w][g + 8]  = p1;
            s_gp[w][g + 16] = p2;
            s_gp[w][g + 24] = p3;
        }
    }
    __syncthreads();

    if (j < TEK)
        s_gate[j] = s_gp[0][j] + s_gp[1][j] + s_gp[2][j] + s_gp[3][j] + bc2[0];
    __syncthreads();

    {
        int e = j >> 2, c = j & 3;    // 128 threads = 32 edges x 4
        int r = s_row[e];
        if (r >= 0) {
            if (c < 3) atomicAdd(&g_dx[r * 3 + c], s_rel[e][c] * s_gate[e]);
            else       atomicAdd(&g_cnt[r], 1.0f);
        }
    }
}

// ---------------------------------------------------------------------------
// Node kernel via tf32 MMA (unchanged from R10)
// ---------------------------------------------------------------------------
__global__ __launch_bounds__(128) void node_kernel(
    const float* __restrict__ x, const float* __restrict__ h, int n,
    const float* __restrict__ bn1, const float* __restrict__ bn2,
    const float* __restrict__ gamma, const float* __restrict__ beta,
    float* __restrict__ xout, float* __restrict__ hout)
{
    __shared__ float s_tf[32][260];
    __shared__ float s_mu[32], s_rs[32];

    const int j = threadIdx.x;
    const int w = j >> 5, lane = j & 31;
    const int g = lane >> 2, tg = lane & 3;
    const int n0 = blockIdx.x * 32;

    const int rowA = lane & 15;
    const int colA = (lane & 16) ? 4 : 0;
    const unsigned baseA0 = (unsigned)__cvta_generic_to_shared(&s_tf[rowA][colA]);
    const unsigned baseA1 = (unsigned)__cvta_generic_to_shared(&s_tf[16 + rowA][colA]);

    #pragma unroll 4
    for (int e = 0; e < 32; e++) {
        int nd = n0 + e;
        float hv = 0.f, av = 0.f;
        if (nd < n) {
            float c = g_cnt[nd]; c = c < 1.0f ? 1.0f : c;
            hv = h[(long)nd * H + j];
            av = g_agg[(long)nd * H + j] / c;
        }
        s_tf[e][j]     = tf32f(hv);
        s_tf[e][H + j] = tf32f(av);
    }
    __syncthreads();

    float cc[4][2][4];

    // ---- GEMM1: n1 = silu(nin @ Wn1 + bn1), K=256 ----
    #pragma unroll
    for (int t = 0; t < 4; t++)
        #pragma unroll
        for (int mt = 0; mt < 2; mt++)
            #pragma unroll
            for (int q = 0; q < 4; q++) cc[t][mt][q] = 0.f;

    #pragma unroll 4
    for (int s = 0; s < 32; s++) {
        unsigned a00, a01, a02, a03, a10, a11, a12, a13;
        ldsm4(a00, a01, a02, a03, baseA0 + 32u * s);
        ldsm4(a10, a11, a12, a13, baseA1 + 32u * s);
        #pragma unroll
        for (int t = 0; t < 4; t++) {
            float2 bv = *(const float2*)&g_Wn1[(((4 * w + t) * 32 + s) * 32 + lane) * 2];
            unsigned b0 = __float_as_uint(bv.x), b1 = __float_as_uint(bv.y);
            mma_tf32(cc[t][0], a00, a01, a02, a03, b0, b1);
            mma_tf32(cc[t][1], a10, a11, a12, a13, b0, b1);
        }
    }
    __syncthreads();

    #pragma unroll
    for (int t = 0; t < 4; t++) {
        int col = 32 * w + 8 * t + 2 * tg;
        float b0 = bn1[col], b1 = bn1[col + 1];
        #pragma unroll
        for (int mt = 0; mt < 2; mt++) {
            int r0 = g + 16 * mt, r1 = r0 + 8;
            s_tf[r0][col]     = tf32f(silu(cc[t][mt][0] + b0));
            s_tf[r0][col + 1] = tf32f(silu(cc[t][mt][1] + b1));
            s_tf[r1][col]     = tf32f(silu(cc[t][mt][2] + b0));
            s_tf[r1][col + 1] = tf32f(silu(cc[t][mt][3] + b1));
        }
    }
    __syncthreads();

    // ---- GEMM2: dh = n1 @ Wn2 + bn2, K=128 ----
    #pragma unroll
    for (int t = 0; t < 4; t++)
        #pragma unroll
        for (int mt = 0; mt < 2; mt++)
            #pragma unroll
            for (int q = 0; q < 4; q++) cc[t][mt][q] = 0.f;

    #pragma unroll 4
    for (int s = 0; s < 16; s++) {
        unsigned a00, a01, a02, a03, a10, a11, a12, a13;
        ldsm4(a00, a01, a02, a03, baseA0 + 32u * s);
        ldsm4(a10, a11, a12, a13, baseA1 + 32u * s);
        #pragma unroll
        for (int t = 0; t < 4; t++) {
            float2 bv = *(const float2*)&g_Wn2[(((4 * w + t) * 16 + s) * 32 + lane) * 2];
            unsigned b0 = __float_as_uint(bv.x), b1 = __float_as_uint(bv.y);
            mma_tf32(cc[t][0], a00, a01, a02, a03, b0, b1);
            mma_tf32(cc[t][1], a10, a11, a12, a13, b0, b1);
        }
    }

    #pragma unroll
    for (int t = 0; t < 4; t++) {
        int col = 32 * w + 8 * t + 2 * tg;
        float b0 = bn2[col], b1 = bn2[col + 1];
        #pragma unroll
        for (int mt = 0; mt < 2; mt++) {
            int r0 = g + 16 * mt, r1 = r0 + 8;
            int nd0 = n0 + r0, nd1 = n0 + r1;
            float h00 = (nd0 < n) ? h[(long)nd0 * H + col]     : 0.f;
            float h01 = (nd0 < n) ? h[(long)nd0 * H + col + 1] : 0.f;
            float h10 = (nd1 < n) ? h[(long)nd1 * H + col]     : 0.f;
            float h11 = (nd1 < n) ? h[(long)nd1 * H + col + 1] : 0.f;
            s_tf[r0][H + col]     = h00 + cc[t][mt][0] + b0;
            s_tf[r0][H + col + 1] = h01 + cc[t][mt][1] + b1;
            s_tf[r1][H + col]     = h10 + cc[t][mt][2] + b0;
            s_tf[r1][H + col + 1] = h11 + cc[t][mt][3] + b1;
        }
    }
    __syncthreads();

    #pragma unroll
    for (int q = 0; q < 8; q++) {
        int e = w * 8 + q;
        float v0 = s_tf[e][H + lane];
        float v1 = s_tf[e][H + lane + 32];
        float v2 = s_tf[e][H + lane + 64];
        float v3 = s_tf[e][H + lane + 96];
        float s  = v0 + v1 + v2 + v3;
        float ss = v0 * v0 + v1 * v1 + v2 * v2 + v3 * v3;
        #pragma unroll
        for (int off = 16; off > 0; off >>= 1) {
            s  += __shfl_down_sync(0xffffffffu, s, off);
            ss += __shfl_down_sync(0xffffffffu, ss, off);
        }
        if (lane == 0) {
            float mu = s * (1.0f / H);
            float var = ss * (1.0f / H) - mu * mu;
            s_mu[e] = mu;
            s_rs[e] = rsqrtf(var + 1e-5f);
        }
    }
    __syncthreads();

    float gj = gamma[j], bj = beta[j];
    #pragma unroll 4
    for (int e = 0; e < 32; e++) {
        int nd = n0 + e;
        if (nd < n) {
            float v = (s_tf[e][H + j] - s_mu[e]) * s_rs[e] * gj + bj;
            hout[(long)nd * H + j] = silu(v);
            if (j < 3) {
                float c = g_cnt[nd]; c = c < 1.0f ? 1.0f : c;
                xout[nd * 3 + j] = x[nd * 3 + j] + g_dx[nd * 3 + j] / c;
            }
        }
    }
}

extern "C" void kernel_launch(void* const* d_in, const int* in_sizes, int n_in,
                              void* d_out, int out_size)
{
    const float* x    = (const float*)d_in[0];
    const float* h    = (const float*)d_in[1];
    const int*   ei   = (const int*)d_in[2];
    const float* We1  = (const float*)d_in[3];
    const float* be1  = (const float*)d_in[4];
    const float* We2  = (const float*)d_in[5];
    const float* be2  = (const float*)d_in[6];
    const float* Wc1  = (const float*)d_in[7];
    const float* bc1  = (const float*)d_in[8];
    const float* Wc2  = (const float*)d_in[9];
    const float* bc2  = (const float*)d_in[10];
    const float* Wn1  = (const float*)d_in[11];
    const float* bn1  = (const float*)d_in[12];
    const float* Wn2  = (const float*)d_in[13];
    const float* bn2  = (const float*)d_in[14];
    const float* gamma = (const float*)d_in[15];
    const float* beta  = (const float*)d_in[16];

    int n = in_sizes[0] / 3;       // 50000
    int E = in_sizes[2] / 2;       // 800000

    float* xout = (float*)d_out;              // [n,3]
    float* hout = xout + (size_t)n * 3;       // [n,128]

    zero_kernel<<<256, 256>>>(n);
    prep_kernel<<<448, 256>>>(We2, Wc1, Wn1, Wn2, We1);
    pq_kernel<<<(n + 31) / 32, 128>>>(h, n);
    edge_kernel<<<(E + TEK - 1) / TEK, 128>>>(x, ei, E,
                                              We1, be1, be2, bc1, Wc2, bc2);
    node_kernel<<<(n + 31) / 32, 128>>>(x, h, n, bn1, bn2,
                                        gamma, beta, xout, hout);
}

// round 13
// speedup vs baseline: 1.3571x; 1.1500x over previous
#include <cuda_runtime.h>
#include <cuda_bf16.h>

#define H 128
#define NMAX 50000
#define TEK 32          // edges per block (edge kernel)

// Scratch (no dynamic allocation allowed)
__device__ float g_agg[NMAX * H];
__device__ float g_dx[NMAX * 3];
__device__ float g_cnt[NMAX];
__device__ float g_P[NMAX * H];        // h @ We1[0:128]
__device__ float g_Q[NMAX * H];        // h @ We1[128:256]
__device__ float g_W2e[16 * 1024];     // We2 tf32 B-frag (v2 layout)
__device__ float g_W1p[16 * 1024];     // We1[0:128]   (v2)
__device__ float g_W1q[16 * 1024];     // We1[128:256] (v2)
__device__ float g_Wn2[16 * 1024];     // Wn2          (v2)
__device__ float g_Wn1[32 * 1024];     // Wn1 (S=32, K=256, v2)
__device__ unsigned g_W2cb[16 * 8 * 32 * 2];  // Wc1 bf16 B-frag pairs (m16n8k16)

__device__ __forceinline__ float silu(float v) {
    return v / (1.0f + __expf(-v));
}
__device__ __forceinline__ unsigned tf32u(float f) {
    unsigned r; asm("cvt.rna.tf32.f32 %0, %1;" : "=r"(r) : "f"(f));
    return r;
}
__device__ __forceinline__ float tf32f(float f) {
    return __uint_as_float(tf32u(f));
}
__device__ __forceinline__ unsigned packbf(float a, float b) {
    __nv_bfloat162 v = __floats2bfloat162_rn(a, b);
    return *(unsigned*)&v;
}
__device__ __forceinline__ void mma_tf32(float c[4],
    unsigned a0, unsigned a1, unsigned a2, unsigned a3,
    unsigned b0, unsigned b1)
{
    asm("mma.sync.aligned.m16n8k8.row.col.f32.tf32.tf32.f32 "
        "{%0,%1,%2,%3},{%4,%5,%6,%7},{%8,%9},{%0,%1,%2,%3};"
        : "+f"(c[0]), "+f"(c[1]), "+f"(c[2]), "+f"(c[3])
        : "r"(a0), "r"(a1), "r"(a2), "r"(a3), "r"(b0), "r"(b1));
}
__device__ __forceinline__ void mma_bf16(float c[4],
    unsigned a0, unsigned a1, unsigned a2, unsigned a3,
    unsigned b0, unsigned b1)
{
    asm("mma.sync.aligned.m16n8k16.row.col.f32.bf16.bf16.f32 "
        "{%0,%1,%2,%3},{%4,%5,%6,%7},{%8,%9},{%0,%1,%2,%3};"
        : "+f"(c[0]), "+f"(c[1]), "+f"(c[2]), "+f"(c[3])
        : "r"(a0), "r"(a1), "r"(a2), "r"(a3), "r"(b0), "r"(b1));
}
__device__ __forceinline__ void ldsm4(unsigned &r0, unsigned &r1,
                                      unsigned &r2, unsigned &r3,
                                      unsigned addr)
{
    asm volatile("ldmatrix.sync.aligned.m8n8.x4.shared.b16 {%0,%1,%2,%3}, [%4];"
        : "=r"(r0), "=r"(r1), "=r"(r2), "=r"(r3) : "r"(addr));
}

__global__ void zero_kernel(int n) {
    int total = n * H + n * 3 + n;
    for (int i = blockIdx.x * blockDim.x + threadIdx.x; i < total;
         i += gridDim.x * blockDim.x) {
        if (i < n * H) g_agg[i] = 0.0f;
        else if (i < n * H + n * 3) g_dx[i - n * H] = 0.0f;
        else g_cnt[i - n * H - n * 3] = 0.0f;
    }
}

// v2 layout: dst[((tp*S+s)*32+lane)*2 + r] = tf32(W[8s+tg+4r][8tp+g])
__device__ __forceinline__ void swz_store(float* dst, const float* W,
                                          int S, int idx)
{
    int r = idx & 1;
    int lane = (idx >> 1) & 31;
    int sp = idx >> 6;             // tp*S + s
    int s = sp % S, tp = sp / S;
    int g = lane >> 2, tg = lane & 3;
    dst[idx] = tf32f(W[(8 * s + tg + 4 * r) * H + 8 * tp + g]);
}

// bf16 B-frag layout for m16n8k16:
// word w of pair: k0 = 16s + 8w + 2tg; value = pack(W[k0][n], W[k0+1][n]), n = 8t+g
__device__ __forceinline__ void swz_store_bf(unsigned* dst, const float* W, int idx)
{
    int wrd = idx & 1;
    int lane = (idx >> 1) & 31;
    int s = (idx >> 6) & 7;
    int t = idx >> 9;
    int g = lane >> 2, tg = lane & 3;
    int k0 = 16 * s + 8 * wrd + 2 * tg;
    int n = 8 * t + g;
    dst[idx] = packbf(W[k0 * H + n], W[(k0 + 1) * H + n]);
}

__global__ void prep_kernel(const float* __restrict__ We2,
                            const float* __restrict__ Wc1,
                            const float* __restrict__ Wn1,
                            const float* __restrict__ Wn2,
                            const float* __restrict__ We1)
{
    int i = blockIdx.x * blockDim.x + threadIdx.x;
    if (i < 16384)       swz_store(g_W2e, We2, 16, i);
    else if (i < 32768)  swz_store(g_W1p, We1, 16, i - 16384);
    else if (i < 49152)  swz_store(g_W1q, We1 + 128 * H, 16, i - 32768);
    else if (i < 65536)  swz_store(g_Wn2, Wn2, 16, i - 49152);
    else if (i < 98304)  swz_store(g_Wn1, Wn1, 32, i - 65536);
    else if (i < 106496) swz_store_bf(g_W2cb, Wc1, i - 98304);
}

// ---------------------------------------------------------------------------
// PQ via tf32 MMA: 32 nodes/block, warps split N (32 cols each).
// ---------------------------------------------------------------------------
__global__ __launch_bounds__(128) void pq_kernel(
    const float* __restrict__ h, int n)
{
    __shared__ float s_tf[32][132];

    const int j = threadIdx.x;
    const int w = j >> 5, lane = j & 31;
    const int g = lane >> 2, tg = lane & 3;
    const int n0 = blockIdx.x * 32;

    const int rowA = lane & 15;
    const int colA = (lane & 16) ? 4 : 0;
    const unsigned baseA0 = (unsigned)__cvta_generic_to_shared(&s_tf[rowA][colA]);
    const unsigned baseA1 = (unsigned)__cvta_generic_to_shared(&s_tf[16 + rowA][colA]);

    #pragma unroll 4
    for (int e = 0; e < 32; e++) {
        int nd = n0 + e;
        s_tf[e][j] = (nd < n) ? tf32f(h[(long)nd * H + j]) : 0.f;
    }
    __syncthreads();

    float cc[4][2][4];

    // ---- P ----
    #pragma unroll
    for (int t = 0; t < 4; t++)
        #pragma unroll
        for (int mt = 0; mt < 2; mt++)
            #pragma unroll
            for (int q = 0; q < 4; q++) cc[t][mt][q] = 0.f;

    #pragma unroll 4
    for (int s = 0; s < 16; s++) {
        unsigned a00, a01, a02, a03, a10, a11, a12, a13;
        ldsm4(a00, a01, a02, a03, baseA0 + 32u * s);
        ldsm4(a10, a11, a12, a13, baseA1 + 32u * s);
        #pragma unroll
        for (int t = 0; t < 4; t++) {
            float2 bv = *(const float2*)&g_W1p[(((4 * w + t) * 16 + s) * 32 + lane) * 2];
            unsigned b0 = __float_as_uint(bv.x), b1 = __float_as_uint(bv.y);
            mma_tf32(cc[t][0], a00, a01, a02, a03, b0, b1);
            mma_tf32(cc[t][1], a10, a11, a12, a13, b0, b1);
        }
    }
    #pragma unroll
    for (int t = 0; t < 4; t++) {
        int col = 32 * w + 8 * t + 2 * tg;
        #pragma unroll
        for (int mt = 0; mt < 2; mt++) {
            int nd0 = n0 + g + 16 * mt, nd1 = nd0 + 8;
            if (nd0 < n) *(float2*)&g_P[(long)nd0 * H + col] =
                make_float2(cc[t][mt][0], cc[t][mt][1]);
            if (nd1 < n) *(float2*)&g_P[(long)nd1 * H + col] =
                make_float2(cc[t][mt][2], cc[t][mt][3]);
        }
    }

    // ---- Q ----
    #pragma unroll
    for (int t = 0; t < 4; t++)
        #pragma unroll
        for (int mt = 0; mt < 2; mt++)
            #pragma unroll
            for (int q = 0; q < 4; q++) cc[t][mt][q] = 0.f;

    #pragma unroll 4
    for (int s = 0; s < 16; s++) {
        unsigned a00, a01, a02, a03, a10, a11, a12, a13;
        ldsm4(a00, a01, a02, a03, baseA0 + 32u * s);
        ldsm4(a10, a11, a12, a13, baseA1 + 32u * s);
        #pragma unroll
        for (int t = 0; t < 4; t++) {
            float2 bv = *(const float2*)&g_W1q[(((4 * w + t) * 16 + s) * 32 + lane) * 2];
            unsigned b0 = __float_as_uint(bv.x), b1 = __float_as_uint(bv.y);
            mma_tf32(cc[t][0], a00, a01, a02, a03, b0, b1);
            mma_tf32(cc[t][1], a10, a11, a12, a13, b0, b1);
        }
    }
    #pragma unroll
    for (int t = 0; t < 4; t++) {
        int col = 32 * w + 8 * t + 2 * tg;
        #pragma unroll
        for (int mt = 0; mt < 2; mt++) {
            int nd0 = n0 + g + 16 * mt, nd1 = nd0 + 8;
            if (nd0 < n) *(float2*)&g_Q[(long)nd0 * H + col] =
                make_float2(cc[t][mt][0], cc[t][mt][1]);
            if (nd1 < n) *(float2*)&g_Q[(long)nd1 * H + col] =
                make_float2(cc[t][mt][2], cc[t][mt][3]);
        }
    }
}

// ---------------------------------------------------------------------------
// Edge kernel: R10 structure; GEMM1 tf32 (float2 B), GEMM2 bf16 m16n8k16.
// ---------------------------------------------------------------------------
__global__ __launch_bounds__(128) void edge_kernel(
    const float* __restrict__ x, const int* __restrict__ ei, int E,
    const float* __restrict__ We1, const float* __restrict__ be1,
    const float* __restrict__ be2, const float* __restrict__ bc1,
    const float* __restrict__ Wc2, const float* __restrict__ bc2)
{
    __shared__ float    s_tf[TEK][132];
    __shared__ unsigned s_bf[TEK][68];   // f2 in packed bf16x2, row = edge
    __shared__ float    s_rel[TEK][3];
    __shared__ float    s_d2[TEK];
    __shared__ int      s_row[TEK], s_col[TEK];
    __shared__ float    s_gp[4][TEK];
    __shared__ float    s_gate[TEK];

    const int j = threadIdx.x;
    const int w = j >> 5, lane = j & 31;
    const int g = lane >> 2, tg = lane & 3;
    const long e0 = (long)blockIdx.x * TEK;

    // tf32 ldmatrix A addresses (GEMM1)
    const int rowA = lane & 15;
    const int colA = (lane & 16) ? 4 : 0;
    const unsigned baseA0 =
        (unsigned)__cvta_generic_to_shared(&s_tf[rowA][colA]);
    const unsigned baseA1 =
        (unsigned)__cvta_generic_to_shared(&s_tf[16 + rowA][colA]);

    // bf16 ldmatrix A addresses (GEMM2): tile = lane>>3, trow = lane&7
    const int tile = lane >> 3, trow = lane & 7;
    const unsigned baseB0 = (unsigned)__cvta_generic_to_shared(
        &s_bf[(tile & 1) * 8 + trow][(tile >> 1) * 4]);
    const unsigned baseB1 = (unsigned)__cvta_generic_to_shared(
        &s_bf[16 + (tile & 1) * 8 + trow][(tile >> 1) * 4]);

    // Phase 0: per-edge scalars
    if (j < TEK) {
        long e = e0 + j;
        int r = -1, c = 0;
        float rx = 0.f, ry = 0.f, rz = 0.f, d2 = 0.f;
        if (e < E) {
            r = ei[e]; c = ei[E + e];
            rx = x[r * 3 + 0] - x[c * 3 + 0];
            ry = x[r * 3 + 1] - x[c * 3 + 1];
            rz = x[r * 3 + 2] - x[c * 3 + 2];
            d2 = rx * rx + ry * ry + rz * rz;
        }
        s_row[j] = r; s_col[j] = c; s_d2[j] = d2;
        s_rel[j][0] = rx; s_rel[j][1] = ry; s_rel[j][2] = rz;
    }
    __syncthreads();

    // Phase 1: layer-1 elementwise (thread j = column j), stored tf32
    {
        float wl = We1[256 * H + j];
        float b  = be1[j];
        #pragma unroll 4
        for (int e = 0; e < TEK; e++) {
            int r = s_row[e], c = s_col[e];
            float v = 0.f;
            if (r >= 0)
                v = silu(g_P[(long)r * H + j] + g_Q[(long)c * H + j]
                         + s_d2[e] * wl + b);
            s_tf[e][j] = tf32f(v);
        }
    }
    __syncthreads();

    float cc[4][2][4];

    // ---- GEMM1 (tf32): f2 = silu(f1 @ We2 + be2) ----
    #pragma unroll
    for (int t = 0; t < 4; t++)
        #pragma unroll
        for (int mt = 0; mt < 2; mt++)
            #pragma unroll
            for (int q = 0; q < 4; q++) cc[t][mt][q] = 0.f;

    #pragma unroll 4
    for (int s = 0; s < 16; s++) {
        unsigned a00, a01, a02, a03, a10, a11, a12, a13;
        ldsm4(a00, a01, a02, a03, baseA0 + 32u * s);
        ldsm4(a10, a11, a12, a13, baseA1 + 32u * s);
        #pragma unroll
        for (int t = 0; t < 4; t++) {
            float2 bv = *(const float2*)&g_W2e[(((4 * w + t) * 16 + s) * 32 + lane) * 2];
            unsigned b0 = __float_as_uint(bv.x), b1 = __float_as_uint(bv.y);
            mma_tf32(cc[t][0], a00, a01, a02, a03, b0, b1);
            mma_tf32(cc[t][1], a10, a11, a12, a13, b0, b1);
        }
    }
    __syncthreads();   // all warps done reading s_tf (f1)

    // epilogue: silu + bias; tf32 -> s_tf (scatter), bf16x2 -> s_bf (GEMM2 A)
    #pragma unroll
    for (int t = 0; t < 4; t++) {
        int col = 32 * w + 8 * t + 2 * tg;
        float b0 = be2[col], b1 = be2[col + 1];
        #pragma unroll
        for (int mt = 0; mt < 2; mt++) {
            int r0 = g + 16 * mt, r1 = r0 + 8;
            float v00 = silu(cc[t][mt][0] + b0);
            float v01 = silu(cc[t][mt][1] + b1);
            float v10 = silu(cc[t][mt][2] + b0);
            float v11 = silu(cc[t][mt][3] + b1);
            s_tf[r0][col]     = tf32f(v00);
            s_tf[r0][col + 1] = tf32f(v01);
            s_tf[r1][col]     = tf32f(v10);
            s_tf[r1][col + 1] = tf32f(v11);
            s_bf[r0][col >> 1] = packbf(v00, v01);
            s_bf[r1][col >> 1] = packbf(v10, v11);
        }
    }
    __syncthreads();

    // agg scatter (coalesced: thread j = column j), tf32-rounded f2
    #pragma unroll 4
    for (int e = 0; e < TEK; e++) {
        int r = s_row[e];
        if (r >= 0) atomicAdd(&g_agg[(long)r * H + j], s_tf[e][j]);
    }

    // ---- GEMM2 (bf16 m16n8k16): gate hidden = silu(f2 @ Wc1 + bc1) ----
    #pragma unroll
    for (int t = 0; t < 4; t++)
        #pragma unroll
        for (int mt = 0; mt < 2; mt++)
            #pragma unroll
            for (int q = 0; q < 4; q++) cc[t][mt][q] = 0.f;

    #pragma unroll 4
    for (int s = 0; s < 8; s++) {
        unsigned a00, a01, a02, a03, a10, a11, a12, a13;
        ldsm4(a00, a01, a02, a03, baseB0 + 32u * s);
        ldsm4(a10, a11, a12, a13, baseB1 + 32u * s);
        #pragma unroll
        for (int t = 0; t < 4; t++) {
            uint2 bv = *(const uint2*)&g_W2cb[(((4 * w + t) * 8 + s) * 32 + lane) * 2];
            mma_bf16(cc[t][0], a00, a01, a02, a03, bv.x, bv.y);
            mma_bf16(cc[t][1], a10, a11, a12, a13, bv.x, bv.y);
        }
    }

    // gate partial dot with Wc2; thread covers edge rows g, g+8, g+16, g+24
    {
        float p0 = 0.f, p1 = 0.f, p2 = 0.f, p3 = 0.f;
        #pragma unroll
        for (int t = 0; t < 4; t++) {
            int col = 32 * w + 8 * t + 2 * tg;
            float w0 = Wc2[col], w1 = Wc2[col + 1];
            float b0 = bc1[col], b1 = bc1[col + 1];
            p0 += silu(cc[t][0][0] + b0) * w0 + silu(cc[t][0][1] + b1) * w1;
            p1 += silu(cc[t][0][2] + b0) * w0 + silu(cc[t][0][3] + b1) * w1;
            p2 += silu(cc[t][1][0] + b0) * w0 + silu(cc[t][1][1] + b1) * w1;
            p3 += silu(cc[t][1][2] + b0) * w0 + silu(cc[t][1][3] + b1) * w1;
        }
        p0 += __shfl_xor_sync(0xffffffffu, p0, 1);
        p0 += __shfl_xor_sync(0xffffffffu, p0, 2);
        p1 += __shfl_xor_sync(0xffffffffu, p1, 1);
        p1 += __shfl_xor_sync(0xffffffffu, p1, 2);
        p2 += __shfl_xor_sync(0xffffffffu, p2, 1);
        p2 += __shfl_xor_sync(0xffffffffu, p2, 2);
        p3 += __shfl_xor_sync(0xffffffffu, p3, 1);
        p3 += __shfl_xor_sync(0xffffffffu, p3, 2);
        if (tg == 0) {
            s_gp[w][g]      = p0;
            s_gp[w][g + 8]  = p1;
            s_gp[w][g + 16] = p2;
            s_gp[w][g + 24] = p3;
        }
    }
    __syncthreads();

    if (j < TEK)
        s_gate[j] = s_gp[0][j] + s_gp[1][j] + s_gp[2][j] + s_gp[3][j] + bc2[0];
    __syncthreads();

    {
        int e = j >> 2, c = j & 3;    // 128 threads = 32 edges x 4
        int r = s_row[e];
        if (r >= 0) {
            if (c < 3) atomicAdd(&g_dx[r * 3 + c], s_rel[e][c] * s_gate[e]);
            else       atomicAdd(&g_cnt[r], 1.0f);
        }
    }
}

// ---------------------------------------------------------------------------
// Node kernel via tf32 MMA (unchanged from R10)
// ---------------------------------------------------------------------------
__global__ __launch_bounds__(128) void node_kernel(
    const float* __restrict__ x, const float* __restrict__ h, int n,
    const float* __restrict__ bn1, const float* __restrict__ bn2,
    const float* __restrict__ gamma, const float* __restrict__ beta,
    float* __restrict__ xout, float* __restrict__ hout)
{
    __shared__ float s_tf[32][260];
    __shared__ float s_mu[32], s_rs[32];

    const int j = threadIdx.x;
    const int w = j >> 5, lane = j & 31;
    const int g = lane >> 2, tg = lane & 3;
    const int n0 = blockIdx.x * 32;

    const int rowA = lane & 15;
    const int colA = (lane & 16) ? 4 : 0;
    const unsigned baseA0 = (unsigned)__cvta_generic_to_shared(&s_tf[rowA][colA]);
    const unsigned baseA1 = (unsigned)__cvta_generic_to_shared(&s_tf[16 + rowA][colA]);

    #pragma unroll 4
    for (int e = 0; e < 32; e++) {
        int nd = n0 + e;
        float hv = 0.f, av = 0.f;
        if (nd < n) {
            float c = g_cnt[nd]; c = c < 1.0f ? 1.0f : c;
            hv = h[(long)nd * H + j];
            av = g_agg[(long)nd * H + j] / c;
        }
        s_tf[e][j]     = tf32f(hv);
        s_tf[e][H + j] = tf32f(av);
    }
    __syncthreads();

    float cc[4][2][4];

    // ---- GEMM1: n1 = silu(nin @ Wn1 + bn1), K=256 ----
    #pragma unroll
    for (int t = 0; t < 4; t++)
        #pragma unroll
        for (int mt = 0; mt < 2; mt++)
            #pragma unroll
            for (int q = 0; q < 4; q++) cc[t][mt][q] = 0.f;

    #pragma unroll 4
    for (int s = 0; s < 32; s++) {
        unsigned a00, a01, a02, a03, a10, a11, a12, a13;
        ldsm4(a00, a01, a02, a03, baseA0 + 32u * s);
        ldsm4(a10, a11, a12, a13, baseA1 + 32u * s);
        #pragma unroll
        for (int t = 0; t < 4; t++) {
            float2 bv = *(const float2*)&g_Wn1[(((4 * w + t) * 32 + s) * 32 + lane) * 2];
            unsigned b0 = __float_as_uint(bv.x), b1 = __float_as_uint(bv.y);
            mma_tf32(cc[t][0], a00, a01, a02, a03, b0, b1);
            mma_tf32(cc[t][1], a10, a11, a12, a13, b0, b1);
        }
    }
    __syncthreads();

    #pragma unroll
    for (int t = 0; t < 4; t++) {
        int col = 32 * w + 8 * t + 2 * tg;
        float b0 = bn1[col], b1 = bn1[col + 1];
        #pragma unroll
        for (int mt = 0; mt < 2; mt++) {
            int r0 = g + 16 * mt, r1 = r0 + 8;
            s_tf[r0][col]     = tf32f(silu(cc[t][mt][0] + b0));
            s_tf[r0][col + 1] = tf32f(silu(cc[t][mt][1] + b1));
            s_tf[r1][col]     = tf32f(silu(cc[t][mt][2] + b0));
            s_tf[r1][col + 1] = tf32f(silu(cc[t][mt][3] + b1));
        }
    }
    __syncthreads();

    // ---- GEMM2: dh = n1 @ Wn2 + bn2, K=128 ----
    #pragma unroll
    for (int t = 0; t < 4; t++)
        #pragma unroll
        for (int mt = 0; mt < 2; mt++)
            #pragma unroll
            for (int q = 0; q < 4; q++) cc[t][mt][q] = 0.f;

    #pragma unroll 4
    for (int s = 0; s < 16; s++) {
        unsigned a00, a01, a02, a03, a10, a11, a12, a13;
        ldsm4(a00, a01, a02, a03, baseA0 + 32u * s);
        ldsm4(a10, a11, a12, a13, baseA1 + 32u * s);
        #pragma unroll
        for (int t = 0; t < 4; t++) {
            float2 bv = *(const float2*)&g_Wn2[(((4 * w + t) * 16 + s) * 32 + lane) * 2];
            unsigned b0 = __float_as_uint(bv.x), b1 = __float_as_uint(bv.y);
            mma_tf32(cc[t][0], a00, a01, a02, a03, b0, b1);
            mma_tf32(cc[t][1], a10, a11, a12, a13, b0, b1);
        }
    }

    #pragma unroll
    for (int t = 0; t < 4; t++) {
        int col = 32 * w + 8 * t + 2 * tg;
        float b0 = bn2[col], b1 = bn2[col + 1];
        #pragma unroll
        for (int mt = 0; mt < 2; mt++) {
            int r0 = g + 16 * mt, r1 = r0 + 8;
            int nd0 = n0 + r0, nd1 = n0 + r1;
            float h00 = (nd0 < n) ? h[(long)nd0 * H + col]     : 0.f;
            float h01 = (nd0 < n) ? h[(long)nd0 * H + col + 1] : 0.f;
            float h10 = (nd1 < n) ? h[(long)nd1 * H + col]     : 0.f;
            float h11 = (nd1 < n) ? h[(long)nd1 * H + col + 1] : 0.f;
            s_tf[r0][H + col]     = h00 + cc[t][mt][0] + b0;
            s_tf[r0][H + col + 1] = h01 + cc[t][mt][1] + b1;
            s_tf[r1][H + col]     = h10 + cc[t][mt][2] + b0;
            s_tf[r1][H + col + 1] = h11 + cc[t][mt][3] + b1;
        }
    }
    __syncthreads();

    #pragma unroll
    for (int q = 0; q < 8; q++) {
        int e = w * 8 + q;
        float v0 = s_tf[e][H + lane];
        float v1 = s_tf[e][H + lane + 32];
        float v2 = s_tf[e][H + lane + 64];
        float v3 = s_tf[e][H + lane + 96];
        float s  = v0 + v1 + v2 + v3;
        float ss = v0 * v0 + v1 * v1 + v2 * v2 + v3 * v3;
        #pragma unroll
        for (int off = 16; off > 0; off >>= 1) {
            s  += __shfl_down_sync(0xffffffffu, s, off);
            ss += __shfl_down_sync(0xffffffffu, ss, off);
        }
        if (lane == 0) {
            float mu = s * (1.0f / H);
            float var = ss * (1.0f / H) - mu * mu;
            s_mu[e] = mu;
            s_rs[e] = rsqrtf(var + 1e-5f);
        }
    }
    __syncthreads();

    float gj = gamma[j], bj = beta[j];
    #pragma unroll 4
    for (int e = 0; e < 32; e++) {
        int nd = n0 + e;
        if (nd < n) {
            float v = (s_tf[e][H + j] - s_mu[e]) * s_rs[e] * gj + bj;
            hout[(long)nd * H + j] = silu(v);
            if (j < 3) {
                float c = g_cnt[nd]; c = c < 1.0f ? 1.0f : c;
                xout[nd * 3 + j] = x[nd * 3 + j] + g_dx[nd * 3 + j] / c;
            }
        }
    }
}

extern "C" void kernel_launch(void* const* d_in, const int* in_sizes, int n_in,
                              void* d_out, int out_size)
{
    const float* x    = (const float*)d_in[0];
    const float* h    = (const float*)d_in[1];
    const int*   ei   = (const int*)d_in[2];
    const float* We1  = (const float*)d_in[3];
    const float* be1  = (const float*)d_in[4];
    const float* We2  = (const float*)d_in[5];
    const float* be2  = (const float*)d_in[6];
    const float* Wc1  = (const float*)d_in[7];
    const float* bc1  = (const float*)d_in[8];
    const float* Wc2  = (const float*)d_in[9];
    const float* bc2  = (const float*)d_in[10];
    const float* Wn1  = (const float*)d_in[11];
    const float* bn1  = (const float*)d_in[12];
    const float* Wn2  = (const float*)d_in[13];
    const float* bn2  = (const float*)d_in[14];
    const float* gamma = (const float*)d_in[15];
    const float* beta  = (const float*)d_in[16];

    int n = in_sizes[0] / 3;       // 50000
    int E = in_sizes[2] / 2;       // 800000

    float* xout = (float*)d_out;              // [n,3]
    float* hout = xout + (size_t)n * 3;       // [n,128]

    zero_kernel<<<256, 256>>>(n);
    prep_kernel<<<416, 256>>>(We2, Wc1, Wn1, Wn2, We1);
    pq_kernel<<<(n + 31) / 32, 128>>>(h, n);
    edge_kernel<<<(E + TEK - 1) / TEK, 128>>>(x, ei, E,
                                              We1, be1, be2, bc1, Wc2, bc2);
    node_kernel<<<(n + 31) / 32, 128>>>(x, h, n, bn1, bn2,
                                        gamma, beta, xout, hout);
}

// round 14
// speedup vs baseline: 1.5015x; 1.1064x over previous
#include <cuda_runtime.h>
#include <cuda_bf16.h>

#define H 128
#define NMAX 50000
#define TEK 32          // edges per block (edge kernel)

// Scratch (no dynamic allocation allowed)
__device__ float g_agg[NMAX * H];
__device__ float g_dx[NMAX * 3];
__device__ float g_cnt[NMAX];
__device__ float g_P[NMAX * H];        // h @ We1[0:128]
__device__ float g_Q[NMAX * H];        // h @ We1[128:256]
__device__ float g_W2e[16 * 1024];     // We2 tf32 B-frag (v2 layout)
__device__ float g_W1p[16 * 1024];     // We1[0:128]   (v2)
__device__ float g_W1q[16 * 1024];     // We1[128:256] (v2)
__device__ float g_Wn2[16 * 1024];     // Wn2          (v2)
__device__ float g_Wn1[32 * 1024];     // Wn1 (S=32, K=256, v2)
__device__ unsigned g_W2cb[16 * 8 * 32 * 2];  // Wc1 bf16 B-frag pairs (m16n8k16)

__device__ __forceinline__ float silu(float v) {
    return v / (1.0f + __expf(-v));
}
__device__ __forceinline__ unsigned tf32u(float f) {
    unsigned r; asm("cvt.rna.tf32.f32 %0, %1;" : "=r"(r) : "f"(f));
    return r;
}
__device__ __forceinline__ float tf32f(float f) {
    return __uint_as_float(tf32u(f));
}
__device__ __forceinline__ unsigned packbf(float a, float b) {
    __nv_bfloat162 v = __floats2bfloat162_rn(a, b);
    return *(unsigned*)&v;
}
__device__ __forceinline__ void mma_tf32(float c[4],
    unsigned a0, unsigned a1, unsigned a2, unsigned a3,
    unsigned b0, unsigned b1)
{
    asm("mma.sync.aligned.m16n8k8.row.col.f32.tf32.tf32.f32 "
        "{%0,%1,%2,%3},{%4,%5,%6,%7},{%8,%9},{%0,%1,%2,%3};"
        : "+f"(c[0]), "+f"(c[1]), "+f"(c[2]), "+f"(c[3])
        : "r"(a0), "r"(a1), "r"(a2), "r"(a3), "r"(b0), "r"(b1));
}
__device__ __forceinline__ void mma_bf16(float c[4],
    unsigned a0, unsigned a1, unsigned a2, unsigned a3,
    unsigned b0, unsigned b1)
{
    asm("mma.sync.aligned.m16n8k16.row.col.f32.bf16.bf16.f32 "
        "{%0,%1,%2,%3},{%4,%5,%6,%7},{%8,%9},{%0,%1,%2,%3};"
        : "+f"(c[0]), "+f"(c[1]), "+f"(c[2]), "+f"(c[3])
        : "r"(a0), "r"(a1), "r"(a2), "r"(a3), "r"(b0), "r"(b1));
}
__device__ __forceinline__ void ldsm4(unsigned &r0, unsigned &r1,
                                      unsigned &r2, unsigned &r3,
                                      unsigned addr)
{
    asm volatile("ldmatrix.sync.aligned.m8n8.x4.shared.b16 {%0,%1,%2,%3}, [%4];"
        : "=r"(r0), "=r"(r1), "=r"(r2), "=r"(r3) : "r"(addr));
}
__device__ __forceinline__ void redv4(float* p, float4 v) {
    asm volatile("red.global.add.v4.f32 [%0], {%1,%2,%3,%4};"
        :: "l"(p), "f"(v.x), "f"(v.y), "f"(v.z), "f"(v.w) : "memory");
}

__global__ void zero_kernel(int n) {
    int total = n * H + n * 3 + n;
    for (int i = blockIdx.x * blockDim.x + threadIdx.x; i < total;
         i += gridDim.x * blockDim.x) {
        if (i < n * H) g_agg[i] = 0.0f;
        else if (i < n * H + n * 3) g_dx[i - n * H] = 0.0f;
        else g_cnt[i - n * H - n * 3] = 0.0f;
    }
}

// v2 layout: dst[((tp*S+s)*32+lane)*2 + r] = tf32(W[8s+tg+4r][8tp+g])
__device__ __forceinline__ void swz_store(float* dst, const float* W,
                                          int S, int idx)
{
    int r = idx & 1;
    int lane = (idx >> 1) & 31;
    int sp = idx >> 6;             // tp*S + s
    int s = sp % S, tp = sp / S;
    int g = lane >> 2, tg = lane & 3;
    dst[idx] = tf32f(W[(8 * s + tg + 4 * r) * H + 8 * tp + g]);
}

// bf16 B-frag layout for m16n8k16
__device__ __forceinline__ void swz_store_bf(unsigned* dst, const float* W, int idx)
{
    int wrd = idx & 1;
    int lane = (idx >> 1) & 31;
    int s = (idx >> 6) & 7;
    int t = idx >> 9;
    int g = lane >> 2, tg = lane & 3;
    int k0 = 16 * s + 8 * wrd + 2 * tg;
    int n = 8 * t + g;
    dst[idx] = packbf(W[k0 * H + n], W[(k0 + 1) * H + n]);
}

__global__ void prep_kernel(const float* __restrict__ We2,
                            const float* __restrict__ Wc1,
                            const float* __restrict__ Wn1,
                            const float* __restrict__ Wn2,
                            const float* __restrict__ We1)
{
    int i = blockIdx.x * blockDim.x + threadIdx.x;
    if (i < 16384)       swz_store(g_W2e, We2, 16, i);
    else if (i < 32768)  swz_store(g_W1p, We1, 16, i - 16384);
    else if (i < 49152)  swz_store(g_W1q, We1 + 128 * H, 16, i - 32768);
    else if (i < 65536)  swz_store(g_Wn2, Wn2, 16, i - 49152);
    else if (i < 98304)  swz_store(g_Wn1, Wn1, 32, i - 65536);
    else if (i < 106496) swz_store_bf(g_W2cb, Wc1, i - 98304);
}

// ---------------------------------------------------------------------------
// PQ via tf32 MMA: 32 nodes/block, warps split N (32 cols each).
// ---------------------------------------------------------------------------
__global__ __launch_bounds__(128) void pq_kernel(
    const float* __restrict__ h, int n)
{
    __shared__ float s_tf[32][132];

    const int j = threadIdx.x;
    const int w = j >> 5, lane = j & 31;
    const int g = lane >> 2, tg = lane & 3;
    const int n0 = blockIdx.x * 32;

    const int rowA = lane & 15;
    const int colA = (lane & 16) ? 4 : 0;
    const unsigned baseA0 = (unsigned)__cvta_generic_to_shared(&s_tf[rowA][colA]);
    const unsigned baseA1 = (unsigned)__cvta_generic_to_shared(&s_tf[16 + rowA][colA]);

    #pragma unroll 4
    for (int e = 0; e < 32; e++) {
        int nd = n0 + e;
        s_tf[e][j] = (nd < n) ? tf32f(h[(long)nd * H + j]) : 0.f;
    }
    __syncthreads();

    float cc[4][2][4];

    // ---- P ----
    #pragma unroll
    for (int t = 0; t < 4; t++)
        #pragma unroll
        for (int mt = 0; mt < 2; mt++)
            #pragma unroll
            for (int q = 0; q < 4; q++) cc[t][mt][q] = 0.f;

    #pragma unroll 4
    for (int s = 0; s < 16; s++) {
        unsigned a00, a01, a02, a03, a10, a11, a12, a13;
        ldsm4(a00, a01, a02, a03, baseA0 + 32u * s);
        ldsm4(a10, a11, a12, a13, baseA1 + 32u * s);
        #pragma unroll
        for (int t = 0; t < 4; t++) {
            float2 bv = *(const float2*)&g_W1p[(((4 * w + t) * 16 + s) * 32 + lane) * 2];
            unsigned b0 = __float_as_uint(bv.x), b1 = __float_as_uint(bv.y);
            mma_tf32(cc[t][0], a00, a01, a02, a03, b0, b1);
            mma_tf32(cc[t][1], a10, a11, a12, a13, b0, b1);
        }
    }
    #pragma unroll
    for (int t = 0; t < 4; t++) {
        int col = 32 * w + 8 * t + 2 * tg;
        #pragma unroll
        for (int mt = 0; mt < 2; mt++) {
            int nd0 = n0 + g + 16 * mt, nd1 = nd0 + 8;
            if (nd0 < n) *(float2*)&g_P[(long)nd0 * H + col] =
                make_float2(cc[t][mt][0], cc[t][mt][1]);
            if (nd1 < n) *(float2*)&g_P[(long)nd1 * H + col] =
                make_float2(cc[t][mt][2], cc[t][mt][3]);
        }
    }

    // ---- Q ----
    #pragma unroll
    for (int t = 0; t < 4; t++)
        #pragma unroll
        for (int mt = 0; mt < 2; mt++)
            #pragma unroll
            for (int q = 0; q < 4; q++) cc[t][mt][q] = 0.f;

    #pragma unroll 4
    for (int s = 0; s < 16; s++) {
        unsigned a00, a01, a02, a03, a10, a11, a12, a13;
        ldsm4(a00, a01, a02, a03, baseA0 + 32u * s);
        ldsm4(a10, a11, a12, a13, baseA1 + 32u * s);
        #pragma unroll
        for (int t = 0; t < 4; t++) {
            float2 bv = *(const float2*)&g_W1q[(((4 * w + t) * 16 + s) * 32 + lane) * 2];
            unsigned b0 = __float_as_uint(bv.x), b1 = __float_as_uint(bv.y);
            mma_tf32(cc[t][0], a00, a01, a02, a03, b0, b1);
            mma_tf32(cc[t][1], a10, a11, a12, a13, b0, b1);
        }
    }
    #pragma unroll
    for (int t = 0; t < 4; t++) {
        int col = 32 * w + 8 * t + 2 * tg;
        #pragma unroll
        for (int mt = 0; mt < 2; mt++) {
            int nd0 = n0 + g + 16 * mt, nd1 = nd0 + 8;
            if (nd0 < n) *(float2*)&g_Q[(long)nd0 * H + col] =
                make_float2(cc[t][mt][0], cc[t][mt][1]);
            if (nd1 < n) *(float2*)&g_Q[(long)nd1 * H + col] =
                make_float2(cc[t][mt][2], cc[t][mt][3]);
        }
    }
}

// ---------------------------------------------------------------------------
// Edge kernel: GEMM1 tf32, GEMM2 bf16; phase-1 gathers and agg scatter
// vectorized to 128-bit ops.
// ---------------------------------------------------------------------------
__global__ __launch_bounds__(128) void edge_kernel(
    const float* __restrict__ x, const int* __restrict__ ei, int E,
    const float* __restrict__ We1, const float* __restrict__ be1,
    const float* __restrict__ be2, const float* __restrict__ bc1,
    const float* __restrict__ Wc2, const float* __restrict__ bc2)
{
    __shared__ float    s_tf[TEK][132];
    __shared__ unsigned s_bf[TEK][68];   // f2 in packed bf16x2
    __shared__ float    s_rel[TEK][3];
    __shared__ float    s_d2[TEK];
    __shared__ int      s_row[TEK], s_col[TEK];
    __shared__ float    s_gp[4][TEK];
    __shared__ float    s_gate[TEK];

    const int j = threadIdx.x;
    const int w = j >> 5, lane = j & 31;
    const int g = lane >> 2, tg = lane & 3;
    const long e0 = (long)blockIdx.x * TEK;

    // tf32 ldmatrix A addresses (GEMM1)
    const int rowA = lane & 15;
    const int colA = (lane & 16) ? 4 : 0;
    const unsigned baseA0 =
        (unsigned)__cvta_generic_to_shared(&s_tf[rowA][colA]);
    const unsigned baseA1 =
        (unsigned)__cvta_generic_to_shared(&s_tf[16 + rowA][colA]);

    // bf16 ldmatrix A addresses (GEMM2)
    const int tile = lane >> 3, trow = lane & 7;
    const unsigned baseB0 = (unsigned)__cvta_generic_to_shared(
        &s_bf[(tile & 1) * 8 + trow][(tile >> 1) * 4]);
    const unsigned baseB1 = (unsigned)__cvta_generic_to_shared(
        &s_bf[16 + (tile & 1) * 8 + trow][(tile >> 1) * 4]);

    // Phase 0: per-edge scalars
    if (j < TEK) {
        long e = e0 + j;
        int r = -1, c = 0;
        float rx = 0.f, ry = 0.f, rz = 0.f, d2 = 0.f;
        if (e < E) {
            r = ei[e]; c = ei[E + e];
            rx = x[r * 3 + 0] - x[c * 3 + 0];
            ry = x[r * 3 + 1] - x[c * 3 + 1];
            rz = x[r * 3 + 2] - x[c * 3 + 2];
            d2 = rx * rx + ry * ry + rz * rz;
        }
        s_row[j] = r; s_col[j] = c; s_d2[j] = d2;
        s_rel[j][0] = rx; s_rel[j][1] = ry; s_rel[j][2] = rz;
    }
    __syncthreads();

    // Phase 1 (vectorized): thread (eg = j>>5) handles cols [4*lane,4*lane+4)
    // of edges eg, eg+4, ..., eg+28. float4 loads of P/Q, float4 STS of tf32.
    {
        const int c4 = lane * 4;
        const float4 wl4 = *(const float4*)&We1[256 * H + c4];
        const float4 b4  = *(const float4*)&be1[c4];
        #pragma unroll
        for (int it = 0; it < 8; it++) {
            int e = (j >> 5) + it * 4;
            int r = s_row[e], c = s_col[e];
            float4 v;
            if (r >= 0) {
                float4 Pv = *(const float4*)&g_P[(long)r * H + c4];
                float4 Qv = *(const float4*)&g_Q[(long)c * H + c4];
                float d2 = s_d2[e];
                v.x = tf32f(silu(Pv.x + Qv.x + d2 * wl4.x + b4.x));
                v.y = tf32f(silu(Pv.y + Qv.y + d2 * wl4.y + b4.y));
                v.z = tf32f(silu(Pv.z + Qv.z + d2 * wl4.z + b4.z));
                v.w = tf32f(silu(Pv.w + Qv.w + d2 * wl4.w + b4.w));
            } else {
                v = make_float4(0.f, 0.f, 0.f, 0.f);
            }
            *(float4*)&s_tf[e][c4] = v;
        }
    }
    __syncthreads();

    float cc[4][2][4];

    // ---- GEMM1 (tf32): f2 = silu(f1 @ We2 + be2) ----
    #pragma unroll
    for (int t = 0; t < 4; t++)
        #pragma unroll
        for (int mt = 0; mt < 2; mt++)
            #pragma unroll
            for (int q = 0; q < 4; q++) cc[t][mt][q] = 0.f;

    #pragma unroll 4
    for (int s = 0; s < 16; s++) {
        unsigned a00, a01, a02, a03, a10, a11, a12, a13;
        ldsm4(a00, a01, a02, a03, baseA0 + 32u * s);
        ldsm4(a10, a11, a12, a13, baseA1 + 32u * s);
        #pragma unroll
        for (int t = 0; t < 4; t++) {
            float2 bv = *(const float2*)&g_W2e[(((4 * w + t) * 16 + s) * 32 + lane) * 2];
            unsigned b0 = __float_as_uint(bv.x), b1 = __float_as_uint(bv.y);
            mma_tf32(cc[t][0], a00, a01, a02, a03, b0, b1);
            mma_tf32(cc[t][1], a10, a11, a12, a13, b0, b1);
        }
    }
    __syncthreads();   // all warps done reading s_tf (f1)

    // epilogue: silu + bias; tf32 -> s_tf (scatter), bf16x2 -> s_bf (GEMM2 A)
    #pragma unroll
    for (int t = 0; t < 4; t++) {
        int col = 32 * w + 8 * t + 2 * tg;
        float b0 = be2[col], b1 = be2[col + 1];
        #pragma unroll
        for (int mt = 0; mt < 2; mt++) {
            int r0 = g + 16 * mt, r1 = r0 + 8;
            float v00 = silu(cc[t][mt][0] + b0);
            float v01 = silu(cc[t][mt][1] + b1);
            float v10 = silu(cc[t][mt][2] + b0);
            float v11 = silu(cc[t][mt][3] + b1);
            s_tf[r0][col]     = tf32f(v00);
            s_tf[r0][col + 1] = tf32f(v01);
            s_tf[r1][col]     = tf32f(v10);
            s_tf[r1][col + 1] = tf32f(v11);
            s_bf[r0][col >> 1] = packbf(v00, v01);
            s_bf[r1][col >> 1] = packbf(v10, v11);
        }
    }
    __syncthreads();

    // agg scatter: vectorized red.v4; warp w covers edges 4*it+w
    #pragma unroll
    for (int it = 0; it < 8; it++) {
        int e = 4 * it + w;
        int r = s_row[e];
        if (r >= 0) {
            float4 v = *(const float4*)&s_tf[e][lane * 4];
            redv4(&g_agg[(long)r * H + lane * 4], v);
        }
    }

    // ---- GEMM2 (bf16 m16n8k16): gate hidden = silu(f2 @ Wc1 + bc1) ----
    #pragma unroll
    for (int t = 0; t < 4; t++)
        #pragma unroll
        for (int mt = 0; mt < 2; mt++)
            #pragma unroll
            for (int q = 0; q < 4; q++) cc[t][mt][q] = 0.f;

    #pragma unroll 4
    for (int s = 0; s < 8; s++) {
        unsigned a00, a01, a02, a03, a10, a11, a12, a13;
        ldsm4(a00, a01, a02, a03, baseB0 + 32u * s);
        ldsm4(a10, a11, a12, a13, baseB1 + 32u * s);
        #pragma unroll
        for (int t = 0; t < 4; t++) {
            uint2 bv = *(const uint2*)&g_W2cb[(((4 * w + t) * 8 + s) * 32 + lane) * 2];
            mma_bf16(cc[t][0], a00, a01, a02, a03, bv.x, bv.y);
            mma_bf16(cc[t][1], a10, a11, a12, a13, bv.x, bv.y);
        }
    }

    // gate partial dot with Wc2
    {
        float p0 = 0.f, p1 = 0.f, p2 = 0.f, p3 = 0.f;
        #pragma unroll
        for (int t = 0; t < 4; t++) {
            int col = 32 * w + 8 * t + 2 * tg;
            float w0 = Wc2[col], w1 = Wc2[col + 1];
            float b0 = bc1[col], b1 = bc1[col + 1];
            p0 += silu(cc[t][0][0] + b0) * w0 + silu(cc[t][0][1] + b1) * w1;
            p1 += silu(cc[t][0][2] + b0) * w0 + silu(cc[t][0][3] + b1) * w1;
            p2 += silu(cc[t][1][0] + b0) * w0 + silu(cc[t][1][1] + b1) * w1;
            p3 += silu(cc[t][1][2] + b0) * w0 + silu(cc[t][1][3] + b1) * w1;
        }
        p0 += __shfl_xor_sync(0xffffffffu, p0, 1);
        p0 += __shfl_xor_sync(0xffffffffu, p0, 2);
        p1 += __shfl_xor_sync(0xffffffffu, p1, 1);
        p1 += __shfl_xor_sync(0xffffffffu, p1, 2);
        p2 += __shfl_xor_sync(0xffffffffu, p2, 1);
        p2 += __shfl_xor_sync(0xffffffffu, p2, 2);
        p3 += __shfl_xor_sync(0xffffffffu, p3, 1);
        p3 += __shfl_xor_sync(0xffffffffu, p3, 2);
        if (tg == 0) {
            s_gp[w][g]      = p0;
            s_gp[w][g + 8]  = p1;
            s_gp[w][g + 16] = p2;
            s_gp[w][g + 24] = p3;
        }
    }
    __syncthreads();

    if (j < TEK)
        s_gate[j] = s_gp[0][j] + s_gp[1][j] + s_gp[2][j] + s_gp[3][j] + bc2[0];
    __syncthreads();

    {
        int e = j >> 2, c = j & 3;    // 128 threads = 32 edges x 4
        int r = s_row[e];
        if (r >= 0) {
            if (c < 3) atomicAdd(&g_dx[r * 3 + c], s_rel[e][c] * s_gate[e]);
            else       atomicAdd(&g_cnt[r], 1.0f);
        }
    }
}

// ---------------------------------------------------------------------------
// Node kernel via tf32 MMA (unchanged)
// ---------------------------------------------------------------------------
__global__ __launch_bounds__(128) void node_kernel(
    const float* __restrict__ x, const float* __restrict__ h, int n,
    const float* __restrict__ bn1, const float* __restrict__ bn2,
    const float* __restrict__ gamma, const float* __restrict__ beta,
    float* __restrict__ xout, float* __restrict__ hout)
{
    __shared__ float s_tf[32][260];
    __shared__ float s_mu[32], s_rs[32];

    const int j = threadIdx.x;
    const int w = j >> 5, lane = j & 31;
    const int g = lane >> 2, tg = lane & 3;
    const int n0 = blockIdx.x * 32;

    const int rowA = lane & 15;
    const int colA = (lane & 16) ? 4 : 0;
    const unsigned baseA0 = (unsigned)__cvta_generic_to_shared(&s_tf[rowA][colA]);
    const unsigned baseA1 = (unsigned)__cvta_generic_to_shared(&s_tf[16 + rowA][colA]);

    #pragma unroll 4
    for (int e = 0; e < 32; e++) {
        int nd = n0 + e;
        float hv = 0.f, av = 0.f;
        if (nd < n) {
            float c = g_cnt[nd]; c = c < 1.0f ? 1.0f : c;
            hv = h[(long)nd * H + j];
            av = g_agg[(long)nd * H + j] / c;
        }
        s_tf[e][j]     = tf32f(hv);
        s_tf[e][H + j] = tf32f(av);
    }
    __syncthreads();

    float cc[4][2][4];

    // ---- GEMM1: n1 = silu(nin @ Wn1 + bn1), K=256 ----
    #pragma unroll
    for (int t = 0; t < 4; t++)
        #pragma unroll
        for (int mt = 0; mt < 2; mt++)
            #pragma unroll
            for (int q = 0; q < 4; q++) cc[t][mt][q] = 0.f;

    #pragma unroll 4
    for (int s = 0; s < 32; s++) {
        unsigned a00, a01, a02, a03, a10, a11, a12, a13;
        ldsm4(a00, a01, a02, a03, baseA0 + 32u * s);
        ldsm4(a10, a11, a12, a13, baseA1 + 32u * s);
        #pragma unroll
        for (int t = 0; t < 4; t++) {
            float2 bv = *(const float2*)&g_Wn1[(((4 * w + t) * 32 + s) * 32 + lane) * 2];
            unsigned b0 = __float_as_uint(bv.x), b1 = __float_as_uint(bv.y);
            mma_tf32(cc[t][0], a00, a01, a02, a03, b0, b1);
            mma_tf32(cc[t][1], a10, a11, a12, a13, b0, b1);
        }
    }
    __syncthreads();

    #pragma unroll
    for (int t = 0; t < 4; t++) {
        int col = 32 * w + 8 * t + 2 * tg;
        float b0 = bn1[col], b1 = bn1[col + 1];
        #pragma unroll
        for (int mt = 0; mt < 2; mt++) {
            int r0 = g + 16 * mt, r1 = r0 + 8;
            s_tf[r0][col]     = tf32f(silu(cc[t][mt][0] + b0));
            s_tf[r0][col + 1] = tf32f(silu(cc[t][mt][1] + b1));
            s_tf[r1][col]     = tf32f(silu(cc[t][mt][2] + b0));
            s_tf[r1][col + 1] = tf32f(silu(cc[t][mt][3] + b1));
        }
    }
    __syncthreads();

    // ---- GEMM2: dh = n1 @ Wn2 + bn2, K=128 ----
    #pragma unroll
    for (int t = 0; t < 4; t++)
        #pragma unroll
        for (int mt = 0; mt < 2; mt++)
            #pragma unroll
            for (int q = 0; q < 4; q++) cc[t][mt][q] = 0.f;

    #pragma unroll 4
    for (int s = 0; s < 16; s++) {
        unsigned a00, a01, a02, a03, a10, a11, a12, a13;
        ldsm4(a00, a01, a02, a03, baseA0 + 32u * s);
        ldsm4(a10, a11, a12, a13, baseA1 + 32u * s);
        #pragma unroll
        for (int t = 0; t < 4; t++) {
            float2 bv = *(const float2*)&g_Wn2[(((4 * w + t) * 16 + s) * 32 + lane) * 2];
            unsigned b0 = __float_as_uint(bv.x), b1 = __float_as_uint(bv.y);
            mma_tf32(cc[t][0], a00, a01, a02, a03, b0, b1);
            mma_tf32(cc[t][1], a10, a11, a12, a13, b0, b1);
        }
    }

    #pragma unroll
    for (int t = 0; t < 4; t++) {
        int col = 32 * w + 8 * t + 2 * tg;
        float b0 = bn2[col], b1 = bn2[col + 1];
        #pragma unroll
        for (int mt = 0; mt < 2; mt++) {
            int r0 = g + 16 * mt, r1 = r0 + 8;
            int nd0 = n0 + r0, nd1 = n0 + r1;
            float h00 = (nd0 < n) ? h[(long)nd0 * H + col]     : 0.f;
            float h01 = (nd0 < n) ? h[(long)nd0 * H + col + 1] : 0.f;
            float h10 = (nd1 < n) ? h[(long)nd1 * H + col]     : 0.f;
            float h11 = (nd1 < n) ? h[(long)nd1 * H + col + 1] : 0.f;
            s_tf[r0][H + col]     = h00 + cc[t][mt][0] + b0;
            s_tf[r0][H + col + 1] = h01 + cc[t][mt][1] + b1;
            s_tf[r1][H + col]     = h10 + cc[t][mt][2] + b0;
            s_tf[r1][H + col + 1] = h11 + cc[t][mt][3] + b1;
        }
    }
    __syncthreads();

    #pragma unroll
    for (int q = 0; q < 8; q++) {
        int e = w * 8 + q;
        float v0 = s_tf[e][H + lane];
        float v1 = s_tf[e][H + lane + 32];
        float v2 = s_tf[e][H + lane + 64];
        float v3 = s_tf[e][H + lane + 96];
        float s  = v0 + v1 + v2 + v3;
        float ss = v0 * v0 + v1 * v1 + v2 * v2 + v3 * v3;
        #pragma unroll
        for (int off = 16; off > 0; off >>= 1) {
            s  += __shfl_down_sync(0xffffffffu, s, off);
            ss += __shfl_down_sync(0xffffffffu, ss, off);
        }
        if (lane == 0) {
            float mu = s * (1.0f / H);
            float var = ss * (1.0f / H) - mu * mu;
            s_mu[e] = mu;
            s_rs[e] = rsqrtf(var + 1e-5f);
        }
    }
    __syncthreads();

    float gj = gamma[j], bj = beta[j];
    #pragma unroll 4
    for (int e = 0; e < 32; e++) {
        int nd = n0 + e;
        if (nd < n) {
            float v = (s_tf[e][H + j] - s_mu[e]) * s_rs[e] * gj + bj;
            hout[(long)nd * H + j] = silu(v);
            if (j < 3) {
                float c = g_cnt[nd]; c = c < 1.0f ? 1.0f : c;
                xout[nd * 3 + j] = x[nd * 3 + j] + g_dx[nd * 3 + j] / c;
            }
        }
    }
}

extern "C" void kernel_launch(void* const* d_in, const int* in_sizes, int n_in,
                              void* d_out, int out_size)
{
    const float* x    = (const float*)d_in[0];
    const float* h    = (const float*)d_in[1];
    const int*   ei   = (const int*)d_in[2];
    const float* We1  = (const float*)d_in[3];
    const float* be1  = (const float*)d_in[4];
    const float* We2  = (const float*)d_in[5];
    const float* be2  = (const float*)d_in[6];
    const float* Wc1  = (const float*)d_in[7];
    const float* bc1  = (const float*)d_in[8];
    const float* Wc2  = (const float*)d_in[9];
    const float* bc2  = (const float*)d_in[10];
    const float* Wn1  = (const float*)d_in[11];
    const float* bn1  = (const float*)d_in[12];
    const float* Wn2  = (const float*)d_in[13];
    const float* bn2  = (const float*)d_in[14];
    const float* gamma = (const float*)d_in[15];
    const float* beta  = (const float*)d_in[16];

    int n = in_sizes[0] / 3;       // 50000
    int E = in_sizes[2] / 2;       // 800000

    float* xout = (float*)d_out;              // [n,3]
    float* hout = xout + (size_t)n * 3;       // [n,128]

    zero_kernel<<<256, 256>>>(n);
    prep_kernel<<<416, 256>>>(We2, Wc1, Wn1, Wn2, We1);
    pq_kernel<<<(n + 31) / 32, 128>>>(h, n);
    edge_kernel<<<(E + TEK - 1) / TEK, 128>>>(x, ei, E,
                                              We1, be1, be2, bc1, Wc2, bc2);
    node_kernel<<<(n + 31) / 32, 128>>>(x, h, n, bn1, bn2,
                                        gamma, beta, xout, hout);
}

// round 15
// speedup vs baseline: 1.6369x; 1.0902x over previous
#include <cuda_runtime.h>
#include <cuda_fp16.h>

#define H 128
#define NMAX 50000
#define TEK 32          // edges per block (edge kernel)

// Scratch (no dynamic allocation allowed)
__device__ float g_agg[NMAX * H];
__device__ float g_dx[NMAX * 3];
__device__ float g_cnt[NMAX];
__device__ float g_P[NMAX * H];        // h @ We1[0:128]
__device__ float g_Q[NMAX * H];        // h @ We1[128:256]
__device__ unsigned g_W2eh[16 * 8 * 32 * 2];  // We2 fp16 B-frag pairs (m16n8k16)
__device__ unsigned g_W2ch[16 * 8 * 32 * 2];  // Wc1 fp16 B-frag pairs
__device__ float g_W1p[16 * 1024];     // We1[0:128]   (tf32 v2)
__device__ float g_W1q[16 * 1024];     // We1[128:256] (tf32 v2)
__device__ float g_Wn2[16 * 1024];     // Wn2          (tf32 v2)
__device__ float g_Wn1[32 * 1024];     // Wn1 (S=32, K=256, tf32 v2)

__device__ __forceinline__ float silu(float v) {
    return v / (1.0f + __expf(-v));
}
__device__ __forceinline__ unsigned tf32u(float f) {
    unsigned r; asm("cvt.rna.tf32.f32 %0, %1;" : "=r"(r) : "f"(f));
    return r;
}
__device__ __forceinline__ float tf32f(float f) {
    return __uint_as_float(tf32u(f));
}
__device__ __forceinline__ unsigned packh(float a, float b) {
    __half2 v = __floats2half2_rn(a, b);
    return *(unsigned*)&v;
}
__device__ __forceinline__ void mma_tf32(float c[4],
    unsigned a0, unsigned a1, unsigned a2, unsigned a3,
    unsigned b0, unsigned b1)
{
    asm("mma.sync.aligned.m16n8k8.row.col.f32.tf32.tf32.f32 "
        "{%0,%1,%2,%3},{%4,%5,%6,%7},{%8,%9},{%0,%1,%2,%3};"
        : "+f"(c[0]), "+f"(c[1]), "+f"(c[2]), "+f"(c[3])
        : "r"(a0), "r"(a1), "r"(a2), "r"(a3), "r"(b0), "r"(b1));
}
__device__ __forceinline__ void mma_f16(float c[4],
    unsigned a0, unsigned a1, unsigned a2, unsigned a3,
    unsigned b0, unsigned b1)
{
    asm("mma.sync.aligned.m16n8k16.row.col.f32.f16.f16.f32 "
        "{%0,%1,%2,%3},{%4,%5,%6,%7},{%8,%9},{%0,%1,%2,%3};"
        : "+f"(c[0]), "+f"(c[1]), "+f"(c[2]), "+f"(c[3])
        : "r"(a0), "r"(a1), "r"(a2), "r"(a3), "r"(b0), "r"(b1));
}
__device__ __forceinline__ void ldsm4(unsigned &r0, unsigned &r1,
                                      unsigned &r2, unsigned &r3,
                                      unsigned addr)
{
    asm volatile("ldmatrix.sync.aligned.m8n8.x4.shared.b16 {%0,%1,%2,%3}, [%4];"
        : "=r"(r0), "=r"(r1), "=r"(r2), "=r"(r3) : "r"(addr));
}
__device__ __forceinline__ void redv4(float* p, float4 v) {
    asm volatile("red.global.add.v4.f32 [%0], {%1,%2,%3,%4};"
        :: "l"(p), "f"(v.x), "f"(v.y), "f"(v.z), "f"(v.w) : "memory");
}

__global__ void zero_kernel(int n) {
    int total = n * H + n * 3 + n;
    for (int i = blockIdx.x * blockDim.x + threadIdx.x; i < total;
         i += gridDim.x * blockDim.x) {
        if (i < n * H) g_agg[i] = 0.0f;
        else if (i < n * H + n * 3) g_dx[i - n * H] = 0.0f;
        else g_cnt[i - n * H - n * 3] = 0.0f;
    }
}

// tf32 v2 layout: dst[((tp*S+s)*32+lane)*2 + r] = tf32(W[8s+tg+4r][8tp+g])
__device__ __forceinline__ void swz_store(float* dst, const float* W,
                                          int S, int idx)
{
    int r = idx & 1;
    int lane = (idx >> 1) & 31;
    int sp = idx >> 6;
    int s = sp % S, tp = sp / S;
    int g = lane >> 2, tg = lane & 3;
    dst[idx] = tf32f(W[(8 * s + tg + 4 * r) * H + 8 * tp + g]);
}

// fp16 B-frag layout for m16n8k16
__device__ __forceinline__ void swz_store_h(unsigned* dst, const float* W, int idx)
{
    int wrd = idx & 1;
    int lane = (idx >> 1) & 31;
    int s = (idx >> 6) & 7;
    int t = idx >> 9;
    int g = lane >> 2, tg = lane & 3;
    int k0 = 16 * s + 8 * wrd + 2 * tg;
    int n = 8 * t + g;
    dst[idx] = packh(W[k0 * H + n], W[(k0 + 1) * H + n]);
}

__global__ void prep_kernel(const float* __restrict__ We2,
                            const float* __restrict__ Wc1,
                            const float* __restrict__ Wn1,
                            const float* __restrict__ Wn2,
                            const float* __restrict__ We1)
{
    int i = blockIdx.x * blockDim.x + threadIdx.x;
    if (i < 8192)        swz_store_h(g_W2eh, We2, i);
    else if (i < 16384)  swz_store_h(g_W2ch, Wc1, i - 8192);
    else if (i < 32768)  swz_store(g_W1p, We1, 16, i - 16384);
    else if (i < 49152)  swz_store(g_W1q, We1 + 128 * H, 16, i - 32768);
    else if (i < 65536)  swz_store(g_Wn2, Wn2, 16, i - 49152);
    else if (i < 98304)  swz_store(g_Wn1, Wn1, 32, i - 65536);
}

// ---------------------------------------------------------------------------
// PQ via tf32 MMA (unchanged)
// ---------------------------------------------------------------------------
__global__ __launch_bounds__(128) void pq_kernel(
    const float* __restrict__ h, int n)
{
    __shared__ float s_tf[32][132];

    const int j = threadIdx.x;
    const int w = j >> 5, lane = j & 31;
    const int g = lane >> 2, tg = lane & 3;
    const int n0 = blockIdx.x * 32;

    const int rowA = lane & 15;
    const int colA = (lane & 16) ? 4 : 0;
    const unsigned baseA0 = (unsigned)__cvta_generic_to_shared(&s_tf[rowA][colA]);
    const unsigned baseA1 = (unsigned)__cvta_generic_to_shared(&s_tf[16 + rowA][colA]);

    #pragma unroll 4
    for (int e = 0; e < 32; e++) {
        int nd = n0 + e;
        s_tf[e][j] = (nd < n) ? tf32f(h[(long)nd * H + j]) : 0.f;
    }
    __syncthreads();

    float cc[4][2][4];

    // ---- P ----
    #pragma unroll
    for (int t = 0; t < 4; t++)
        #pragma unroll
        for (int mt = 0; mt < 2; mt++)
            #pragma unroll
            for (int q = 0; q < 4; q++) cc[t][mt][q] = 0.f;

    #pragma unroll 4
    for (int s = 0; s < 16; s++) {
        unsigned a00, a01, a02, a03, a10, a11, a12, a13;
        ldsm4(a00, a01, a02, a03, baseA0 + 32u * s);
        ldsm4(a10, a11, a12, a13, baseA1 + 32u * s);
        #pragma unroll
        for (int t = 0; t < 4; t++) {
            float2 bv = *(const float2*)&g_W1p[(((4 * w + t) * 16 + s) * 32 + lane) * 2];
            unsigned b0 = __float_as_uint(bv.x), b1 = __float_as_uint(bv.y);
            mma_tf32(cc[t][0], a00, a01, a02, a03, b0, b1);
            mma_tf32(cc[t][1], a10, a11, a12, a13, b0, b1);
        }
    }
    #pragma unroll
    for (int t = 0; t < 4; t++) {
        int col = 32 * w + 8 * t + 2 * tg;
        #pragma unroll
        for (int mt = 0; mt < 2; mt++) {
            int nd0 = n0 + g + 16 * mt, nd1 = nd0 + 8;
            if (nd0 < n) *(float2*)&g_P[(long)nd0 * H + col] =
                make_float2(cc[t][mt][0], cc[t][mt][1]);
            if (nd1 < n) *(float2*)&g_P[(long)nd1 * H + col] =
                make_float2(cc[t][mt][2], cc[t][mt][3]);
        }
    }

    // ---- Q ----
    #pragma unroll
    for (int t = 0; t < 4; t++)
        #pragma unroll
        for (int mt = 0; mt < 2; mt++)
            #pragma unroll
            for (int q = 0; q < 4; q++) cc[t][mt][q] = 0.f;

    #pragma unroll 4
    for (int s = 0; s < 16; s++) {
        unsigned a00, a01, a02, a03, a10, a11, a12, a13;
        ldsm4(a00, a01, a02, a03, baseA0 + 32u * s);
        ldsm4(a10, a11, a12, a13, baseA1 + 32u * s);
        #pragma unroll
        for (int t = 0; t < 4; t++) {
            float2 bv = *(const float2*)&g_W1q[(((4 * w + t) * 16 + s) * 32 + lane) * 2];
            unsigned b0 = __float_as_uint(bv.x), b1 = __float_as_uint(bv.y);
            mma_tf32(cc[t][0], a00, a01, a02, a03, b0, b1);
            mma_tf32(cc[t][1], a10, a11, a12, a13, b0, b1);
        }
    }
    #pragma unroll
    for (int t = 0; t < 4; t++) {
        int col = 32 * w + 8 * t + 2 * tg;
        #pragma unroll
        for (int mt = 0; mt < 2; mt++) {
            int nd0 = n0 + g + 16 * mt, nd1 = nd0 + 8;
            if (nd0 < n) *(float2*)&g_Q[(long)nd0 * H + col] =
                make_float2(cc[t][mt][0], cc[t][mt][1]);
            if (nd1 < n) *(float2*)&g_Q[(long)nd1 * H + col] =
                make_float2(cc[t][mt][2], cc[t][mt][3]);
        }
    }
}

// ---------------------------------------------------------------------------
// Edge kernel: both GEMMs fp16 m16n8k16. Single packed-fp16 smem buffer
// (f1, then f2); scatter unpacks fp16 -> fp32 exactly and uses red.v4.
// ---------------------------------------------------------------------------
__global__ __launch_bounds__(128) void edge_kernel(
    const float* __restrict__ x, const int* __restrict__ ei, int E,
    const float* __restrict__ We1, const float* __restrict__ be1,
    const float* __restrict__ be2, const float* __restrict__ bc1,
    const float* __restrict__ Wc2, const float* __restrict__ bc2)
{
    __shared__ unsigned s_h[TEK][68];    // packed fp16x2, 64 data + 4 pad
    __shared__ float    s_rel[TEK][3];
    __shared__ float    s_d2[TEK];
    __shared__ int      s_row[TEK], s_col[TEK];
    __shared__ float    s_gp[4][TEK];
    __shared__ float    s_gate[TEK];

    const int j = threadIdx.x;
    const int w = j >> 5, lane = j & 31;
    const int g = lane >> 2, tg = lane & 3;
    const long e0 = (long)blockIdx.x * TEK;

    // fp16 ldmatrix A addresses (both GEMMs)
    const int tile = lane >> 3, trow = lane & 7;
    const unsigned baseB0 = (unsigned)__cvta_generic_to_shared(
        &s_h[(tile & 1) * 8 + trow][(tile >> 1) * 4]);
    const unsigned baseB1 = (unsigned)__cvta_generic_to_shared(
        &s_h[16 + (tile & 1) * 8 + trow][(tile >> 1) * 4]);

    // Phase 0: per-edge scalars
    if (j < TEK) {
        long e = e0 + j;
        int r = -1, c = 0;
        float rx = 0.f, ry = 0.f, rz = 0.f, d2 = 0.f;
        if (e < E) {
            r = ei[e]; c = ei[E + e];
            rx = x[r * 3 + 0] - x[c * 3 + 0];
            ry = x[r * 3 + 1] - x[c * 3 + 1];
            rz = x[r * 3 + 2] - x[c * 3 + 2];
            d2 = rx * rx + ry * ry + rz * rz;
        }
        s_row[j] = r; s_col[j] = c; s_d2[j] = d2;
        s_rel[j][0] = rx; s_rel[j][1] = ry; s_rel[j][2] = rz;
    }
    __syncthreads();

    // Phase 1 (vectorized): thread (j>>5) handles cols [4*lane, 4*lane+4)
    // of edges (j>>5)+4*it; float4 P/Q loads, packed fp16x2 store.
    {
        const int c4 = lane * 4;
        const float4 wl4 = *(const float4*)&We1[256 * H + c4];
        const float4 b4  = *(const float4*)&be1[c4];
        #pragma unroll
        for (int it = 0; it < 8; it++) {
            int e = (j >> 5) + it * 4;
            int r = s_row[e], c = s_col[e];
            uint2 u = make_uint2(0u, 0u);
            if (r >= 0) {
                float4 Pv = *(const float4*)&g_P[(long)r * H + c4];
                float4 Qv = *(const float4*)&g_Q[(long)c * H + c4];
                float d2 = s_d2[e];
                float vx = silu(Pv.x + Qv.x + d2 * wl4.x + b4.x);
                float vy = silu(Pv.y + Qv.y + d2 * wl4.y + b4.y);
                float vz = silu(Pv.z + Qv.z + d2 * wl4.z + b4.z);
                float vw = silu(Pv.w + Qv.w + d2 * wl4.w + b4.w);
                u.x = packh(vx, vy);
                u.y = packh(vz, vw);
            }
            *(uint2*)&s_h[e][lane * 2] = u;
        }
    }
    __syncthreads();

    float cc[4][2][4];

    // ---- GEMM1 (fp16): f2 = silu(f1 @ We2 + be2) ----
    #pragma unroll
    for (int t = 0; t < 4; t++)
        #pragma unroll
        for (int mt = 0; mt < 2; mt++)
            #pragma unroll
            for (int q = 0; q < 4; q++) cc[t][mt][q] = 0.f;

    #pragma unroll 4
    for (int s = 0; s < 8; s++) {
        unsigned a00, a01, a02, a03, a10, a11, a12, a13;
        ldsm4(a00, a01, a02, a03, baseB0 + 32u * s);
        ldsm4(a10, a11, a12, a13, baseB1 + 32u * s);
        #pragma unroll
        for (int t = 0; t < 4; t++) {
            uint2 bv = *(const uint2*)&g_W2eh[(((4 * w + t) * 8 + s) * 32 + lane) * 2];
            mma_f16(cc[t][0], a00, a01, a02, a03, bv.x, bv.y);
            mma_f16(cc[t][1], a10, a11, a12, a13, bv.x, bv.y);
        }
    }
    __syncthreads();   // all warps done reading s_h (f1)

    // epilogue: silu + bias -> packed fp16x2 into s_h (GEMM2 A + scatter src)
    #pragma unroll
    for (int t = 0; t < 4; t++) {
        int col = 32 * w + 8 * t + 2 * tg;
        float b0 = be2[col], b1 = be2[col + 1];
        #pragma unroll
        for (int mt = 0; mt < 2; mt++) {
            int r0 = g + 16 * mt, r1 = r0 + 8;
            s_h[r0][col >> 1] = packh(silu(cc[t][mt][0] + b0),
                                      silu(cc[t][mt][1] + b1));
            s_h[r1][col >> 1] = packh(silu(cc[t][mt][2] + b0),
                                      silu(cc[t][mt][3] + b1));
        }
    }
    __syncthreads();

    // agg scatter: unpack fp16 (exact) + red.v4; warp w covers edges 4*it+w
    #pragma unroll
    for (int it = 0; it < 8; it++) {
        int e = 4 * it + w;
        int r = s_row[e];
        if (r >= 0) {
            uint2 u = *(const uint2*)&s_h[e][lane * 2];
            float2 a = __half22float2(*(__half2*)&u.x);
            float2 b = __half22float2(*(__half2*)&u.y);
            redv4(&g_agg[(long)r * H + lane * 4],
                  make_float4(a.x, a.y, b.x, b.y));
        }
    }

    // ---- GEMM2 (fp16): gate hidden = silu(f2 @ Wc1 + bc1) ----
    #pragma unroll
    for (int t = 0; t < 4; t++)
        #pragma unroll
        for (int mt = 0; mt < 2; mt++)
            #pragma unroll
            for (int q = 0; q < 4; q++) cc[t][mt][q] = 0.f;

    #pragma unroll 4
    for (int s = 0; s < 8; s++) {
        unsigned a00, a01, a02, a03, a10, a11, a12, a13;
        ldsm4(a00, a01, a02, a03, baseB0 + 32u * s);
        ldsm4(a10, a11, a12, a13, baseB1 + 32u * s);
        #pragma unroll
        for (int t = 0; t < 4; t++) {
            uint2 bv = *(const uint2*)&g_W2ch[(((4 * w + t) * 8 + s) * 32 + lane) * 2];
            mma_f16(cc[t][0], a00, a01, a02, a03, bv.x, bv.y);
            mma_f16(cc[t][1], a10, a11, a12, a13, bv.x, bv.y);
        }
    }

    // gate partial dot with Wc2
    {
        float p0 = 0.f, p1 = 0.f, p2 = 0.f, p3 = 0.f;
        #pragma unroll
        for (int t = 0; t < 4; t++) {
            int col = 32 * w + 8 * t + 2 * tg;
            float w0 = Wc2[col], w1 = Wc2[col + 1];
            float b0 = bc1[col], b1 = bc1[col + 1];
            p0 += silu(cc[t][0][0] + b0) * w0 + silu(cc[t][0][1] + b1) * w1;
            p1 += silu(cc[t][0][2] + b0) * w0 + silu(cc[t][0][3] + b1) * w1;
            p2 += silu(cc[t][1][0] + b0) * w0 + silu(cc[t][1][1] + b1) * w1;
            p3 += silu(cc[t][1][2] + b0) * w0 + silu(cc[t][1][3] + b1) * w1;
        }
        p0 += __shfl_xor_sync(0xffffffffu, p0, 1);
        p0 += __shfl_xor_sync(0xffffffffu, p0, 2);
        p1 += __shfl_xor_sync(0xffffffffu, p1, 1);
        p1 += __shfl_xor_sync(0xffffffffu, p1, 2);
        p2 += __shfl_xor_sync(0xffffffffu, p2, 1);
        p2 += __shfl_xor_sync(0xffffffffu, p2, 2);
        p3 += __shfl_xor_sync(0xffffffffu, p3, 1);
        p3 += __shfl_xor_sync(0xffffffffu, p3, 2);
        if (tg == 0) {
            s_gp[w][g]      = p0;
            s_gp[w][g + 8]  = p1;
            s_gp[w][g + 16] = p2;
            s_gp[w][g + 24] = p3;
        }
    }
    __syncthreads();

    if (j < TEK)
        s_gate[j] = s_gp[0][j] + s_gp[1][j] + s_gp[2][j] + s_gp[3][j] + bc2[0];
    __syncthreads();

    {
        int e = j >> 2, c = j & 3;    // 128 threads = 32 edges x 4
        int r = s_row[e];
        if (r >= 0) {
            if (c < 3) atomicAdd(&g_dx[r * 3 + c], s_rel[e][c] * s_gate[e]);
            else       atomicAdd(&g_cnt[r], 1.0f);
        }
    }
}

// ---------------------------------------------------------------------------
// Node kernel via tf32 MMA (unchanged)
// ---------------------------------------------------------------------------
__global__ __launch_bounds__(128) void node_kernel(
    const float* __restrict__ x, const float* __restrict__ h, int n,
    const float* __restrict__ bn1, const float* __restrict__ bn2,
    const float* __restrict__ gamma, const float* __restrict__ beta,
    float* __restrict__ xout, float* __restrict__ hout)
{
    __shared__ float s_tf[32][260];
    __shared__ float s_mu[32], s_rs[32];

    const int j = threadIdx.x;
    const int w = j >> 5, lane = j & 31;
    const int g = lane >> 2, tg = lane & 3;
    const int n0 = blockIdx.x * 32;

    const int rowA = lane & 15;
    const int colA = (lane & 16) ? 4 : 0;
    const unsigned baseA0 = (unsigned)__cvta_generic_to_shared(&s_tf[rowA][colA]);
    const unsigned baseA1 = (unsigned)__cvta_generic_to_shared(&s_tf[16 + rowA][colA]);

    #pragma unroll 4
    for (int e = 0; e < 32; e++) {
        int nd = n0 + e;
        float hv = 0.f, av = 0.f;
        if (nd < n) {
            float c = g_cnt[nd]; c = c < 1.0f ? 1.0f : c;
            hv = h[(long)nd * H + j];
            av = g_agg[(long)nd * H + j] / c;
        }
        s_tf[e][j]     = tf32f(hv);
        s_tf[e][H + j] = tf32f(av);
    }
    __syncthreads();

    float cc[4][2][4];

    // ---- GEMM1: n1 = silu(nin @ Wn1 + bn1), K=256 ----
    #pragma unroll
    for (int t = 0; t < 4; t++)
        #pragma unroll
        for (int mt = 0; mt < 2; mt++)
            #pragma unroll
            for (int q = 0; q < 4; q++) cc[t][mt][q] = 0.f;

    #pragma unroll 4
    for (int s = 0; s < 32; s++) {
        unsigned a00, a01, a02, a03, a10, a11, a12, a13;
        ldsm4(a00, a01, a02, a03, baseA0 + 32u * s);
        ldsm4(a10, a11, a12, a13, baseA1 + 32u * s);
        #pragma unroll
        for (int t = 0; t < 4; t++) {
            float2 bv = *(const float2*)&g_Wn1[(((4 * w + t) * 32 + s) * 32 + lane) * 2];
            unsigned b0 = __float_as_uint(bv.x), b1 = __float_as_uint(bv.y);
            mma_tf32(cc[t][0], a00, a01, a02, a03, b0, b1);
            mma_tf32(cc[t][1], a10, a11, a12, a13, b0, b1);
        }
    }
    __syncthreads();

    #pragma unroll
    for (int t = 0; t < 4; t++) {
        int col = 32 * w + 8 * t + 2 * tg;
        float b0 = bn1[col], b1 = bn1[col + 1];
        #pragma unroll
        for (int mt = 0; mt < 2; mt++) {
            int r0 = g + 16 * mt, r1 = r0 + 8;
            s_tf[r0][col]     = tf32f(silu(cc[t][mt][0] + b0));
            s_tf[r0][col + 1] = tf32f(silu(cc[t][mt][1] + b1));
            s_tf[r1][col]     = tf32f(silu(cc[t][mt][2] + b0));
            s_tf[r1][col + 1] = tf32f(silu(cc[t][mt][3] + b1));
        }
    }
    __syncthreads();

    // ---- GEMM2: dh = n1 @ Wn2 + bn2, K=128 ----
    #pragma unroll
    for (int t = 0; t < 4; t++)
        #pragma unroll
        for (int mt = 0; mt < 2; mt++)
            #pragma unroll
            for (int q = 0; q < 4; q++) cc[t][mt][q] = 0.f;

    #pragma unroll 4
    for (int s = 0; s < 16; s++) {
        unsigned a00, a01, a02, a03, a10, a11, a12, a13;
        ldsm4(a00, a01, a02, a03, baseA0 + 32u * s);
        ldsm4(a10, a11, a12, a13, baseA1 + 32u * s);
        #pragma unroll
        for (int t = 0; t < 4; t++) {
            float2 bv = *(const float2*)&g_Wn2[(((4 * w + t) * 16 + s) * 32 + lane) * 2];
            unsigned b0 = __float_as_uint(bv.x), b1 = __float_as_uint(bv.y);
            mma_tf32(cc[t][0], a00, a01, a02, a03, b0, b1);
            mma_tf32(cc[t][1], a10, a11, a12, a13, b0, b1);
        }
    }

    #pragma unroll
    for (int t = 0; t < 4; t++) {
        int col = 32 * w + 8 * t + 2 * tg;
        float b0 = bn2[col], b1 = bn2[col + 1];
        #pragma unroll
        for (int mt = 0; mt < 2; mt++) {
            int r0 = g + 16 * mt, r1 = r0 + 8;
            int nd0 = n0 + r0, nd1 = n0 + r1;
            float h00 = (nd0 < n) ? h[(long)nd0 * H + col]     : 0.f;
            float h01 = (nd0 < n) ? h[(long)nd0 * H + col + 1] : 0.f;
            float h10 = (nd1 < n) ? h[(long)nd1 * H + col]     : 0.f;
            float h11 = (nd1 < n) ? h[(long)nd1 * H + col + 1] : 0.f;
            s_tf[r0][H + col]     = h00 + cc[t][mt][0] + b0;
            s_tf[r0][H + col + 1] = h01 + cc[t][mt][1] + b1;
            s_tf[r1][H + col]     = h10 + cc[t][mt][2] + b0;
            s_tf[r1][H + col + 1] = h11 + cc[t][mt][3] + b1;
        }
    }
    __syncthreads();

    #pragma unroll
    for (int q = 0; q < 8; q++) {
        int e = w * 8 + q;
        float v0 = s_tf[e][H + lane];
        float v1 = s_tf[e][H + lane + 32];
        float v2 = s_tf[e][H + lane + 64];
        float v3 = s_tf[e][H + lane + 96];
        float s  = v0 + v1 + v2 + v3;
        float ss = v0 * v0 + v1 * v1 + v2 * v2 + v3 * v3;
        #pragma unroll
        for (int off = 16; off > 0; off >>= 1) {
            s  += __shfl_down_sync(0xffffffffu, s, off);
            ss += __shfl_down_sync(0xffffffffu, ss, off);
        }
        if (lane == 0) {
            float mu = s * (1.0f / H);
            float var = ss * (1.0f / H) - mu * mu;
            s_mu[e] = mu;
            s_rs[e] = rsqrtf(var + 1e-5f);
        }
    }
    __syncthreads();

    float gj = gamma[j], bj = beta[j];
    #pragma unroll 4
    for (int e = 0; e < 32; e++) {
        int nd = n0 + e;
        if (nd < n) {
            float v = (s_tf[e][H + j] - s_mu[e]) * s_rs[e] * gj + bj;
            hout[(long)nd * H + j] = silu(v);
            if (j < 3) {
                float c = g_cnt[nd]; c = c < 1.0f ? 1.0f : c;
                xout[nd * 3 + j] = x[nd * 3 + j] + g_dx[nd * 3 + j] / c;
            }
        }
    }
}

extern "C" void kernel_launch(void* const* d_in, const int* in_sizes, int n_in,
                              void* d_out, int out_size)
{
    const float* x    = (const float*)d_in[0];
    const float* h    = (const float*)d_in[1];
    const int*   ei   = (const int*)d_in[2];
    const float* We1  = (const float*)d_in[3];
    const float* be1  = (const float*)d_in[4];
    const float* We2  = (const float*)d_in[5];
    const float* be2  = (const float*)d_in[6];
    const float* Wc1  = (const float*)d_in[7];
    const float* bc1  = (const float*)d_in[8];
    const float* Wc2  = (const float*)d_in[9];
    const float* bc2  = (const float*)d_in[10];
    const float* Wn1  = (const float*)d_in[11];
    const float* bn1  = (const float*)d_in[12];
    const float* Wn2  = (const float*)d_in[13];
    const float* bn2  = (const float*)d_in[14];
    const float* gamma = (const float*)d_in[15];
    const float* beta  = (const float*)d_in[16];

    int n = in_sizes[0] / 3;       // 50000
    int E = in_sizes[2] / 2;       // 800000

    float* xout = (float*)d_out;              // [n,3]
    float* hout = xout + (size_t)n * 3;       // [n,128]

    zero_kernel<<<256, 256>>>(n);
    prep_kernel<<<384, 256>>>(We2, Wc1, Wn1, Wn2, We1);
    pq_kernel<<<(n + 31) / 32, 128>>>(h, n);
    edge_kernel<<<(E + TEK - 1) / TEK, 128>>>(x, ei, E,
                                              We1, be1, be2, bc1, Wc2, bc2);
    node_kernel<<<(n + 31) / 32, 128>>>(x, h, n, bn1, bn2,
                                        gamma, beta, xout, hout);
}

// round 17
// speedup vs baseline: 2.3624x; 1.4432x over previous
#include <cuda_runtime.h>
#include <cuda_fp16.h>

#define H 128
#define NMAX 50000
#define TEK 32          // edges per block (edge kernel)

// Scratch (no dynamic allocation allowed)
__device__ float g_agg[NMAX * H];
__device__ float g_dx[NMAX * 3];
__device__ float g_cnt[NMAX];
__device__ float g_P[NMAX * H];        // h @ We1[0:128]
__device__ float g_Q[NMAX * H];        // h @ We1[128:256]
__device__ unsigned g_W2eh[16 * 8 * 32 * 2];  // We2 fp16 B-frag pairs (m16n8k16)
__device__ unsigned g_W2ch[16 * 8 * 32 * 2];  // Wc1 fp16 B-frag pairs
__device__ float g_W1p[16 * 1024];     // We1[0:128]   (tf32 v2)
__device__ float g_W1q[16 * 1024];     // We1[128:256] (tf32 v2)
__device__ float g_Wn2[16 * 1024];     // Wn2          (tf32 v2)
__device__ float g_Wn1[32 * 1024];     // Wn1 (S=32, K=256, tf32 v2)

// Fast SiLU: __fdividef -> MUFU.RCP + FMUL instead of full IEEE div sequence.
__device__ __forceinline__ float silu(float v) {
    return __fdividef(v, 1.0f + __expf(-v));
}
__device__ __forceinline__ unsigned tf32u(float f) {
    unsigned r; asm("cvt.rna.tf32.f32 %0, %1;" : "=r"(r) : "f"(f));
    return r;
}
__device__ __forceinline__ float tf32f(float f) {
    return __uint_as_float(tf32u(f));
}
__device__ __forceinline__ unsigned packh(float a, float b) {
    __half2 v = __floats2half2_rn(a, b);
    return *(unsigned*)&v;
}
__device__ __forceinline__ void mma_tf32(float c[4],
    unsigned a0, unsigned a1, unsigned a2, unsigned a3,
    unsigned b0, unsigned b1)
{
    asm("mma.sync.aligned.m16n8k8.row.col.f32.tf32.tf32.f32 "
        "{%0,%1,%2,%3},{%4,%5,%6,%7},{%8,%9},{%0,%1,%2,%3};"
        : "+f"(c[0]), "+f"(c[1]), "+f"(c[2]), "+f"(c[3])
        : "r"(a0), "r"(a1), "r"(a2), "r"(a3), "r"(b0), "r"(b1));
}
__device__ __forceinline__ void mma_f16(float c[4],
    unsigned a0, unsigned a1, unsigned a2, unsigned a3,
    unsigned b0, unsigned b1)
{
    asm("mma.sync.aligned.m16n8k16.row.col.f32.f16.f16.f32 "
        "{%0,%1,%2,%3},{%4,%5,%6,%7},{%8,%9},{%0,%1,%2,%3};"
        : "+f"(c[0]), "+f"(c[1]), "+f"(c[2]), "+f"(c[3])
        : "r"(a0), "r"(a1), "r"(a2), "r"(a3), "r"(b0), "r"(b1));
}
__device__ __forceinline__ void ldsm4(unsigned &r0, unsigned &r1,
                                      unsigned &r2, unsigned &r3,
                                      unsigned addr)
{
    asm volatile("ldmatrix.sync.aligned.m8n8.x4.shared.b16 {%0,%1,%2,%3}, [%4];"
        : "=r"(r0), "=r"(r1), "=r"(r2), "=r"(r3) : "r"(addr));
}
__device__ __forceinline__ void redv4(float* p, float4 v) {
    asm volatile("red.global.add.v4.f32 [%0], {%1,%2,%3,%4};"
        :: "l"(p), "f"(v.x), "f"(v.y), "f"(v.z), "f"(v.w) : "memory");
}

__global__ void zero_kernel(int n) {
    int total = n * H + n * 3 + n;
    for (int i = blockIdx.x * blockDim.x + threadIdx.x; i < total;
         i += gridDim.x * blockDim.x) {
        if (i < n * H) g_agg[i] = 0.0f;
        else if (i < n * H + n * 3) g_dx[i - n * H] = 0.0f;
        else g_cnt[i - n * H - n * 3] = 0.0f;
    }
}

// tf32 v2 layout: dst[((tp*S+s)*32+lane)*2 + r] = tf32(W[8s+tg+4r][8tp+g])
__device__ __forceinline__ void swz_store(float* dst, const float* W,
                                          int S, int idx)
{
    int r = idx & 1;
    int lane = (idx >> 1) & 31;
    int sp = idx >> 6;
    int s = sp % S, tp = sp / S;
    int g = lane >> 2, tg = lane & 3;
    dst[idx] = tf32f(W[(8 * s + tg + 4 * r) * H + 8 * tp + g]);
}

// fp16 B-frag layout for m16n8k16
__device__ __forceinline__ void swz_store_h(unsigned* dst, const float* W, int idx)
{
    int wrd = idx & 1;
    int lane = (idx >> 1) & 31;
    int s = (idx >> 6) & 7;
    int t = idx >> 9;
    int g = lane >> 2, tg = lane & 3;
    int k0 = 16 * s + 8 * wrd + 2 * tg;
    int n = 8 * t + g;
    dst[idx] = packh(W[k0 * H + n], W[(k0 + 1) * H + n]);
}

__global__ void prep_kernel(const float* __restrict__ We2,
                            const float* __restrict__ Wc1,
                            const float* __restrict__ Wn1,
                            const float* __restrict__ Wn2,
                            const float* __restrict__ We1)
{
    int i = blockIdx.x * blockDim.x + threadIdx.x;
    if (i < 8192)        swz_store_h(g_W2eh, We2, i);
    else if (i < 16384)  swz_store_h(g_W2ch, Wc1, i - 8192);
    else if (i < 32768)  swz_store(g_W1p, We1, 16, i - 16384);
    else if (i < 49152)  swz_store(g_W1q, We1 + 128 * H, 16, i - 32768);
    else if (i < 65536)  swz_store(g_Wn2, Wn2, 16, i - 49152);
    else if (i < 98304)  swz_store(g_Wn1, Wn1, 32, i - 65536);
}

// ---------------------------------------------------------------------------
// PQ via tf32 MMA (unchanged)
// ---------------------------------------------------------------------------
__global__ __launch_bounds__(128) void pq_kernel(
    const float* __restrict__ h, int n)
{
    __shared__ float s_tf[32][132];

    const int j = threadIdx.x;
    const int w = j >> 5, lane = j & 31;
    const int g = lane >> 2, tg = lane & 3;
    const int n0 = blockIdx.x * 32;

    const int rowA = lane & 15;
    const int colA = (lane & 16) ? 4 : 0;
    const unsigned baseA0 = (unsigned)__cvta_generic_to_shared(&s_tf[rowA][colA]);
    const unsigned baseA1 = (unsigned)__cvta_generic_to_shared(&s_tf[16 + rowA][colA]);

    #pragma unroll 4
    for (int e = 0; e < 32; e++) {
        int nd = n0 + e;
        s_tf[e][j] = (nd < n) ? tf32f(h[(long)nd * H + j]) : 0.f;
    }
    __syncthreads();

    float cc[4][2][4];

    // ---- P ----
    #pragma unroll
    for (int t = 0; t < 4; t++)
        #pragma unroll
        for (int mt = 0; mt < 2; mt++)
            #pragma unroll
            for (int q = 0; q < 4; q++) cc[t][mt][q] = 0.f;

    #pragma unroll 4
    for (int s = 0; s < 16; s++) {
        unsigned a00, a01, a02, a03, a10, a11, a12, a13;
        ldsm4(a00, a01, a02, a03, baseA0 + 32u * s);
        ldsm4(a10, a11, a12, a13, baseA1 + 32u * s);
        #pragma unroll
        for (int t = 0; t < 4; t++) {
            float2 bv = *(const float2*)&g_W1p[(((4 * w + t) * 16 + s) * 32 + lane) * 2];
            unsigned b0 = __float_as_uint(bv.x), b1 = __float_as_uint(bv.y);
            mma_tf32(cc[t][0], a00, a01, a02, a03, b0, b1);
            mma_tf32(cc[t][1], a10, a11, a12, a13, b0, b1);
        }
    }
    #pragma unroll
    for (int t = 0; t < 4; t++) {
        int col = 32 * w + 8 * t + 2 * tg;
        #pragma unroll
        for (int mt = 0; mt < 2; mt++) {
            int nd0 = n0 + g + 16 * mt, nd1 = nd0 + 8;
            if (nd0 < n) *(float2*)&g_P[(long)nd0 * H + col] =
                make_float2(cc[t][mt][0], cc[t][mt][1]);
            if (nd1 < n) *(float2*)&g_P[(long)nd1 * H + col] =
                make_float2(cc[t][mt][2], cc[t][mt][3]);
        }
    }

    // ---- Q ----
    #pragma unroll
    for (int t = 0; t < 4; t++)
        #pragma unroll
        for (int mt = 0; mt < 2; mt++)
            #pragma unroll
            for (int q = 0; q < 4; q++) cc[t][mt][q] = 0.f;

    #pragma unroll 4
    for (int s = 0; s < 16; s++) {
        unsigned a00, a01, a02, a03, a10, a11, a12, a13;
        ldsm4(a00, a01, a02, a03, baseA0 + 32u * s);
        ldsm4(a10, a11, a12, a13, baseA1 + 32u * s);
        #pragma unroll
        for (int t = 0; t < 4; t++) {
            float2 bv = *(const float2*)&g_W1q[(((4 * w + t) * 16 + s) * 32 + lane) * 2];
            unsigned b0 = __float_as_uint(bv.x), b1 = __float_as_uint(bv.y);
            mma_tf32(cc[t][0], a00, a01, a02, a03, b0, b1);
            mma_tf32(cc[t][1], a10, a11, a12, a13, b0, b1);
        }
    }
    #pragma unroll
    for (int t = 0; t < 4; t++) {
        int col = 32 * w + 8 * t + 2 * tg;
        #pragma unroll
        for (int mt = 0; mt < 2; mt++) {
            int nd0 = n0 + g + 16 * mt, nd1 = nd0 + 8;
            if (nd0 < n) *(float2*)&g_Q[(long)nd0 * H + col] =
                make_float2(cc[t][mt][0], cc[t][mt][1]);
            if (nd1 < n) *(float2*)&g_Q[(long)nd1 * H + col] =
                make_float2(cc[t][mt][2], cc[t][mt][3]);
        }
    }
}

// ---------------------------------------------------------------------------
// Edge kernel: both GEMMs fp16 m16n8k16; fast-silu everywhere.
// ---------------------------------------------------------------------------
__global__ __launch_bounds__(128) void edge_kernel(
    const float* __restrict__ x, const int* __restrict__ ei, int E,
    const float* __restrict__ We1, const float* __restrict__ be1,
    const float* __restrict__ be2, const float* __restrict__ bc1,
    const float* __restrict__ Wc2, const float* __restrict__ bc2)
{
    __shared__ unsigned s_h[TEK][68];    // packed fp16x2, 64 data + 4 pad
    __shared__ float    s_rel[TEK][3];
    __shared__ float    s_d2[TEK];
    __shared__ int      s_row[TEK], s_col[TEK];
    __shared__ float    s_gp[4][TEK];
    __shared__ float    s_gate[TEK];

    const int j = threadIdx.x;
    const int w = j >> 5, lane = j & 31;
    const int g = lane >> 2, tg = lane & 3;
    const long e0 = (long)blockIdx.x * TEK;

    // fp16 ldmatrix A addresses (both GEMMs)
    const int tile = lane >> 3, trow = lane & 7;
    const unsigned baseB0 = (unsigned)__cvta_generic_to_shared(
        &s_h[(tile & 1) * 8 + trow][(tile >> 1) * 4]);
    const unsigned baseB1 = (unsigned)__cvta_generic_to_shared(
        &s_h[16 + (tile & 1) * 8 + trow][(tile >> 1) * 4]);

    // Phase 0: per-edge scalars
    if (j < TEK) {
        long e = e0 + j;
        int r = -1, c = 0;
        float rx = 0.f, ry = 0.f, rz = 0.f, d2 = 0.f;
        if (e < E) {
            r = ei[e]; c = ei[E + e];
            rx = x[r * 3 + 0] - x[c * 3 + 0];
            ry = x[r * 3 + 1] - x[c * 3 + 1];
            rz = x[r * 3 + 2] - x[c * 3 + 2];
            d2 = rx * rx + ry * ry + rz * rz;
        }
        s_row[j] = r; s_col[j] = c; s_d2[j] = d2;
        s_rel[j][0] = rx; s_rel[j][1] = ry; s_rel[j][2] = rz;
    }
    __syncthreads();

    // Phase 1 (vectorized): thread (j>>5) handles cols [4*lane, 4*lane+4)
    {
        const int c4 = lane * 4;
        const float4 wl4 = *(const float4*)&We1[256 * H + c4];
        const float4 b4  = *(const float4*)&be1[c4];
        #pragma unroll
        for (int it = 0; it < 8; it++) {
            int e = (j >> 5) + it * 4;
            int r = s_row[e], c = s_col[e];
            uint2 u = make_uint2(0u, 0u);
            if (r >= 0) {
                float4 Pv = *(const float4*)&g_P[(long)r * H + c4];
                float4 Qv = *(const float4*)&g_Q[(long)c * H + c4];
                float d2 = s_d2[e];
                float vx = silu(Pv.x + Qv.x + d2 * wl4.x + b4.x);
                float vy = silu(Pv.y + Qv.y + d2 * wl4.y + b4.y);
                float vz = silu(Pv.z + Qv.z + d2 * wl4.z + b4.z);
                float vw = silu(Pv.w + Qv.w + d2 * wl4.w + b4.w);
                u.x = packh(vx, vy);
                u.y = packh(vz, vw);
            }
            *(uint2*)&s_h[e][lane * 2] = u;
        }
    }
    __syncthreads();

    float cc[4][2][4];

    // ---- GEMM1 (fp16): f2 = silu(f1 @ We2 + be2) ----
    #pragma unroll
    for (int t = 0; t < 4; t++)
        #pragma unroll
        for (int mt = 0; mt < 2; mt++)
            #pragma unroll
            for (int q = 0; q < 4; q++) cc[t][mt][q] = 0.f;

    #pragma unroll 4
    for (int s = 0; s < 8; s++) {
        unsigned a00, a01, a02, a03, a10, a11, a12, a13;
        ldsm4(a00, a01, a02, a03, baseB0 + 32u * s);
        ldsm4(a10, a11, a12, a13, baseB1 + 32u * s);
        #pragma unroll
        for (int t = 0; t < 4; t++) {
            uint2 bv = *(const uint2*)&g_W2eh[(((4 * w + t) * 8 + s) * 32 + lane) * 2];
            mma_f16(cc[t][0], a00, a01, a02, a03, bv.x, bv.y);
            mma_f16(cc[t][1], a10, a11, a12, a13, bv.x, bv.y);
        }
    }
    __syncthreads();   // all warps done reading s_h (f1)

    // epilogue: silu + bias -> packed fp16x2 into s_h
    #pragma unroll
    for (int t = 0; t < 4; t++) {
        int col = 32 * w + 8 * t + 2 * tg;
        float b0 = be2[col], b1 = be2[col + 1];
        #pragma unroll
        for (int mt = 0; mt < 2; mt++) {
            int r0 = g + 16 * mt, r1 = r0 + 8;
            s_h[r0][col >> 1] = packh(silu(cc[t][mt][0] + b0),
                                      silu(cc[t][mt][1] + b1));
            s_h[r1][col >> 1] = packh(silu(cc[t][mt][2] + b0),
                                      silu(cc[t][mt][3] + b1));
        }
    }
    __syncthreads();

    // agg scatter: unpack fp16 (exact) + red.v4; warp w covers edges 4*it+w
    #pragma unroll
    for (int it = 0; it < 8; it++) {
        int e = 4 * it + w;
        int r = s_row[e];
        if (r >= 0) {
            uint2 u = *(const uint2*)&s_h[e][lane * 2];
            float2 a = __half22float2(*(__half2*)&u.x);
            float2 b = __half22float2(*(__half2*)&u.y);
            redv4(&g_agg[(long)r * H + lane * 4],
                  make_float4(a.x, a.y, b.x, b.y));
        }
    }

    // ---- GEMM2 (fp16): gate hidden = silu(f2 @ Wc1 + bc1) ----
    #pragma unroll
    for (int t = 0; t < 4; t++)
        #pragma unroll
        for (int mt = 0; mt < 2; mt++)
            #pragma unroll
            for (int q = 0; q < 4; q++) cc[t][mt][q] = 0.f;

    #pragma unroll 4
    for (int s = 0; s < 8; s++) {
        unsigned a00, a01, a02, a03, a10, a11, a12, a13;
        ldsm4(a00, a01, a02, a03, baseB0 + 32u * s);
        ldsm4(a10, a11, a12, a13, baseB1 + 32u * s);
        #pragma unroll
        for (int t = 0; t < 4; t++) {
            uint2 bv = *(const uint2*)&g_W2ch[(((4 * w + t) * 8 + s) * 32 + lane) * 2];
            mma_f16(cc[t][0], a00, a01, a02, a03, bv.x, bv.y);
            mma_f16(cc[t][1], a10, a11, a12, a13, bv.x, bv.y);
        }
    }

    // gate partial dot with Wc2
    {
        float p0 = 0.f, p1 = 0.f, p2 = 0.f, p3 = 0.f;
        #pragma unroll
        for (int t = 0; t < 4; t++) {
            int col = 32 * w + 8 * t + 2 * tg;
            float w0 = Wc2[col], w1 = Wc2[col + 1];
            float b0 = bc1[col], b1 = bc1[col + 1];
            p0 += silu(cc[t][0][0] + b0) * w0 + silu(cc[t][0][1] + b1) * w1;
            p1 += silu(cc[t][0][2] + b0) * w0 + silu(cc[t][0][3] + b1) * w1;
            p2 += silu(cc[t][1][0] + b0) * w0 + silu(cc[t][1][1] + b1) * w1;
            p3 += silu(cc[t][1][2] + b0) * w0 + silu(cc[t][1][3] + b1) * w1;
        }
        p0 += __shfl_xor_sync(0xffffffffu, p0, 1);
        p0 += __shfl_xor_sync(0xffffffffu, p0, 2);
        p1 += __shfl_xor_sync(0xffffffffu, p1, 1);
        p1 += __shfl_xor_sync(0xffffffffu, p1, 2);
        p2 += __shfl_xor_sync(0xffffffffu, p2, 1);
        p2 += __shfl_xor_sync(0xffffffffu, p2, 2);
        p3 += __shfl_xor_sync(0xffffffffu, p3, 1);
        p3 += __shfl_xor_sync(0xffffffffu, p3, 2);
        if (tg == 0) {
            s_gp[w][g]      = p0;
            s_gp[w][g + 8]  = p1;
            s_gp[w][g + 16] = p2;
            s_gp[w][g + 24] = p3;
        }
    }
    __syncthreads();

    if (j < TEK)
        s_gate[j] = s_gp[0][j] + s_gp[1][j] + s_gp[2][j] + s_gp[3][j] + bc2[0];
    __syncthreads();

    {
        int e = j >> 2, c = j & 3;    // 128 threads = 32 edges x 4
        int r = s_row[e];
        if (r >= 0) {
            if (c < 3) atomicAdd(&g_dx[r * 3 + c], s_rel[e][c] * s_gate[e]);
            else       atomicAdd(&g_cnt[r], 1.0f);
        }
    }
}

// ---------------------------------------------------------------------------
// Node kernel via tf32 MMA (fast-silu)
// ---------------------------------------------------------------------------
__global__ __launch_bounds__(128) void node_kernel(
    const float* __restrict__ x, const float* __restrict__ h, int n,
    const float* __restrict__ bn1, const float* __restrict__ bn2,
    const float* __restrict__ gamma, const float* __restrict__ beta,
    float* __restrict__ xout, float* __restrict__ hout)
{
    __shared__ float s_tf[32][260];
    __shared__ float s_mu[32], s_rs[32];

    const int j = threadIdx.x;
    const int w = j >> 5, lane = j & 31;
    const int g = lane >> 2, tg = lane & 3;
    const int n0 = blockIdx.x * 32;

    const int rowA = lane & 15;
    const int colA = (lane & 16) ? 4 : 0;
    const unsigned baseA0 = (unsigned)__cvta_generic_to_shared(&s_tf[rowA][colA]);
    const unsigned baseA1 = (unsigned)__cvta_generic_to_shared(&s_tf[16 + rowA][colA]);

    #pragma unroll 4
    for (int e = 0; e < 32; e++) {
        int nd = n0 + e;
        float hv = 0.f, av = 0.f;
        if (nd < n) {
            float c = g_cnt[nd]; c = c < 1.0f ? 1.0f : c;
            hv = h[(long)nd * H + j];
            av = g_agg[(long)nd * H + j] / c;
        }
        s_tf[e][j]     = tf32f(hv);
        s_tf[e][H + j] = tf32f(av);
    }
    __syncthreads();

    float cc[4][2][4];

    // ---- GEMM1: n1 = silu(nin @ Wn1 + bn1), K=256 ----
    #pragma unroll
    for (int t = 0; t < 4; t++)
        #pragma unroll
        for (int mt = 0; mt < 2; mt++)
            #pragma unroll
            for (int q = 0; q < 4; q++) cc[t][mt][q] = 0.f;

    #pragma unroll 4
    for (int s = 0; s < 32; s++) {
        unsigned a00, a01, a02, a03, a10, a11, a12, a13;
        ldsm4(a00, a01, a02, a03, baseA0 + 32u * s);
        ldsm4(a10, a11, a12, a13, baseA1 + 32u * s);
        #pragma unroll
        for (int t = 0; t < 4; t++) {
            float2 bv = *(const float2*)&g_Wn1[(((4 * w + t) * 32 + s) * 32 + lane) * 2];
            unsigned b0 = __float_as_uint(bv.x), b1 = __float_as_uint(bv.y);
            mma_tf32(cc[t][0], a00, a01, a02, a03, b0, b1);
            mma_tf32(cc[t][1], a10, a11, a12, a13, b0, b1);
        }
    }
    __syncthreads();

    #pragma unroll
    for (int t = 0; t < 4; t++) {
        int col = 32 * w + 8 * t + 2 * tg;
        float b0 = bn1[col], b1 = bn1[col + 1];
        #pragma unroll
        for (int mt = 0; mt < 2; mt++) {
            int r0 = g + 16 * mt, r1 = r0 + 8;
            s_tf[r0][col]     = tf32f(silu(cc[t][mt][0] + b0));
            s_tf[r0][col + 1] = tf32f(silu(cc[t][mt][1] + b1));
            s_tf[r1][col]     = tf32f(silu(cc[t][mt][2] + b0));
            s_tf[r1][col + 1] = tf32f(silu(cc[t][mt][3] + b1));
        }
    }
    __syncthreads();

    // ---- GEMM2: dh = n1 @ Wn2 + bn2, K=128 ----
    #pragma unroll
    for (int t = 0; t < 4; t++)
        #pragma unroll
        for (int mt = 0; mt < 2; mt++)
            #pragma unroll
            for (int q = 0; q < 4; q++) cc[t][mt][q] = 0.f;

    #pragma unroll 4
    for (int s = 0; s < 16; s++) {
        unsigned a00, a01, a02, a03, a10, a11, a12, a13;
        ldsm4(a00, a01, a02, a03, baseA0 + 32u * s);
        ldsm4(a10, a11, a12, a13, baseA1 + 32u * s);
        #pragma unroll
        for (int t = 0; t < 4; t++) {
            float2 bv = *(const float2*)&g_Wn2[(((4 * w + t) * 16 + s) * 32 + lane) * 2];
            unsigned b0 = __float_as_uint(bv.x), b1 = __float_as_uint(bv.y);
            mma_tf32(cc[t][0], a00, a01, a02, a03, b0, b1);
            mma_tf32(cc[t][1], a10, a11, a12, a13, b0, b1);
        }
    }

    #pragma unroll
    for (int t = 0; t < 4; t++) {
        int col = 32 * w + 8 * t + 2 * tg;
        float b0 = bn2[col], b1 = bn2[col + 1];
        #pragma unroll
        for (int mt = 0; mt < 2; mt++) {
            int r0 = g + 16 * mt, r1 = r0 + 8;
            int nd0 = n0 + r0, nd1 = n0 + r1;
            float h00 = (nd0 < n) ? h[(long)nd0 * H + col]     : 0.f;
            float h01 = (nd0 < n) ? h[(long)nd0 * H + col + 1] : 0.f;
            float h10 = (nd1 < n) ? h[(long)nd1 * H + col]     : 0.f;
            float h11 = (nd1 < n) ? h[(long)nd1 * H + col + 1] : 0.f;
            s_tf[r0][H + col]     = h00 + cc[t][mt][0] + b0;
            s_tf[r0][H + col + 1] = h01 + cc[t][mt][1] + b1;
            s_tf[r1][H + col]     = h10 + cc[t][mt][2] + b0;
            s_tf[r1][H + col + 1] = h11 + cc[t][mt][3] + b1;
        }
    }
    __syncthreads();

    #pragma unroll
    for (int q = 0; q < 8; q++) {
        int e = w * 8 + q;
        float v0 = s_tf[e][H + lane];
        float v1 = s_tf[e][H + lane + 32];
        float v2 = s_tf[e][H + lane + 64];
        float v3 = s_tf[e][H + lane + 96];
        float s  = v0 + v1 + v2 + v3;
        float ss = v0 * v0 + v1 * v1 + v2 * v2 + v3 * v3;
        #pragma unroll
        for (int off = 16; off > 0; off >>= 1) {
            s  += __shfl_down_sync(0xffffffffu, s, off);
            ss += __shfl_down_sync(0xffffffffu, ss, off);
        }
        if (lane == 0) {
            float mu = s * (1.0f / H);
            float var = ss * (1.0f / H) - mu * mu;
            s_mu[e] = mu;
            s_rs[e] = rsqrtf(var + 1e-5f);
        }
    }
    __syncthreads();

    float gj = gamma[j], bj = beta[j];
    #pragma unroll 4
    for (int e = 0; e < 32; e++) {
        int nd = n0 + e;
        if (nd < n) {
            float v = (s_tf[e][H + j] - s_mu[e]) * s_rs[e] * gj + bj;
            hout[(long)nd * H + j] = silu(v);
            if (j < 3) {
                float c = g_cnt[nd]; c = c < 1.0f ? 1.0f : c;
                xout[nd * 3 + j] = x[nd * 3 + j] + g_dx[nd * 3 + j] / c;
            }
        }
    }
}

extern "C" void kernel_launch(void* const* d_in, const int* in_sizes, int n_in,
                              void* d_out, int out_size)
{
    const float* x    = (const float*)d_in[0];
    const float* h    = (const float*)d_in[1];
    const int*   ei   = (const int*)d_in[2];
    const float* We1  = (const float*)d_in[3];
    const float* be1  = (const float*)d_in[4];
    const float* We2  = (const float*)d_in[5];
    const float* be2  = (const float*)d_in[6];
    const float* Wc1  = (const float*)d_in[7];
    const float* bc1  = (const float*)d_in[8];
    const float* Wc2  = (const float*)d_in[9];
    const float* bc2  = (const float*)d_in[10];
    const float* Wn1  = (const float*)d_in[11];
    const float* bn1  = (const float*)d_in[12];
    const float* Wn2  = (const float*)d_in[13];
    const float* bn2  = (const float*)d_in[14];
    const float* gamma = (const float*)d_in[15];
    const float* beta  = (const float*)d_in[16];

    int n = in_sizes[0] / 3;       // 50000
    int E = in_sizes[2] / 2;       // 800000

    float* xout = (float*)d_out;              // [n,3]
    float* hout = xout + (size_t)n * 3;       // [n,128]

    zero_kernel<<<256, 256>>>(n);
    prep_kernel<<<384, 256>>>(We2, Wc1, Wn1, Wn2, We1);
    pq_kernel<<<(n + 31) / 32, 128>>>(h, n);
    edge_kernel<<<(E + TEK - 1) / TEK, 128>>>(x, ei, E,
                                              We1, be1, be2, bc1, Wc2, bc2);
    node_kernel<<<(n + 31) / 32, 128>>>(x, h, n, bn1, bn2,
                                        gamma, beta, xout, hout);
}